// round 2
// baseline (speedup 1.0000x reference)
#include <cuda_runtime.h>
#include <cuda_bf16.h>

#define B_ 2
#define S_ 2048
#define E_ 2048
#define H_ 16
#define HD_ 64
#define ROWS_ (B_ * S_)          // 4096
#define LAMBDA_INIT_F 0.783605766532f
#define OUT_SCALE_F   0.216394233468f   // 1 - LAMBDA_INIT

// ---------------- scratch (device globals; no allocations) ----------------
__device__ float g_Q[ROWS_ * E_];     // [B,S,2H,HD] = [4096,2048]
__device__ float g_K[ROWS_ * E_];
__device__ float g_V[ROWS_ * E_];     // [B,S,H,2HD]
__device__ float g_A[ROWS_ * E_];     // attention output pre-Wo
__device__ float g_cos[S_ * 32];
__device__ float g_sin[S_ * 32];
__device__ float g_lambda;

// ---------------- prep: rope tables ----------------
__global__ void prep_tables_kernel() {
    int t = blockIdx.x;        // 0..2047
    int i = threadIdx.x;       // 0..31
    // inv_freq = 10000^(-2i/64); compute in double then trunc to f32 (matches np closely)
    float inv = (float)pow(10000.0, -(double)i / 32.0);
    float f = (float)t * inv;
    g_cos[t * 32 + i] = cosf(f);
    g_sin[t * 32 + i] = sinf(f);
}

// ---------------- prep: lambda scalar ----------------
__global__ void prep_lambda_kernel(const float* __restrict__ lq1, const float* __restrict__ lk1,
                                   const float* __restrict__ lq2, const float* __restrict__ lk2) {
    __shared__ float s1[64], s2[64];
    int i = threadIdx.x;
    s1[i] = lq1[i] * lk1[i];
    s2[i] = lq2[i] * lk2[i];
    __syncthreads();
    if (i == 0) {
        float a = 0.f, b = 0.f;
        for (int j = 0; j < 64; j++) { a += s1[j]; b += s2[j]; }
        g_lambda = expf(a) - expf(b) + LAMBDA_INIT_F;
    }
}

// ---------------- SGEMM: C[M,N] = A[M,K] @ B[K,N], fp32, 128x128x8 tiles ----------------
__global__ __launch_bounds__(256) void sgemm_kernel(
    const float* __restrict__ A, const float* __restrict__ B, float* __restrict__ C,
    int M, int N, int K)
{
    __shared__ float As[8][128];
    __shared__ float Bs[8][128];
    int tid = threadIdx.x;
    int brow = blockIdx.y * 128;
    int bcol = blockIdx.x * 128;

    int arow = tid >> 1;            // 0..127
    int acol = (tid & 1) << 2;      // 0 or 4
    int brl  = tid >> 5;            // 0..7
    int bcl  = (tid & 31) << 2;     // 0..124

    int trow = (tid >> 4) << 3;     // 0..120
    int tcol = (tid & 15) << 3;

    float acc[8][8];
    #pragma unroll
    for (int i = 0; i < 8; i++)
        #pragma unroll
        for (int j = 0; j < 8; j++) acc[i][j] = 0.f;

    for (int k0 = 0; k0 < K; k0 += 8) {
        float4 a4 = *(const float4*)&A[(long)(brow + arow) * K + k0 + acol];
        As[acol + 0][arow] = a4.x;
        As[acol + 1][arow] = a4.y;
        As[acol + 2][arow] = a4.z;
        As[acol + 3][arow] = a4.w;
        *(float4*)&Bs[brl][bcl] = *(const float4*)&B[(long)(k0 + brl) * N + bcol + bcl];
        __syncthreads();

        #pragma unroll
        for (int kk = 0; kk < 8; kk++) {
            float4 a0 = *(float4*)&As[kk][trow];
            float4 a1 = *(float4*)&As[kk][trow + 4];
            float4 b0 = *(float4*)&Bs[kk][tcol];
            float4 b1 = *(float4*)&Bs[kk][tcol + 4];
            float ar[8] = {a0.x, a0.y, a0.z, a0.w, a1.x, a1.y, a1.z, a1.w};
            float br[8] = {b0.x, b0.y, b0.z, b0.w, b1.x, b1.y, b1.z, b1.w};
            #pragma unroll
            for (int i = 0; i < 8; i++)
                #pragma unroll
                for (int j = 0; j < 8; j++)
                    acc[i][j] += ar[i] * br[j];
        }
        __syncthreads();
    }

    #pragma unroll
    for (int i = 0; i < 8; i++) {
        #pragma unroll
        for (int j = 0; j < 8; j += 4) {
            float4 v = make_float4(acc[i][j], acc[i][j + 1], acc[i][j + 2], acc[i][j + 3]);
            *(float4*)&C[(long)(brow + trow + i) * N + bcol + tcol + j] = v;
        }
    }
}

// ---------------- RoPE (interleaved) on Q and K in place ----------------
// grid: (ROWS_*32*32/256, 2); y=0 -> Q, y=1 -> K
__global__ void rope_kernel() {
    int idx = blockIdx.x * 256 + threadIdx.x;       // < 4096*1024
    int row  = idx >> 10;                            // b*S + s
    int rem  = idx & 1023;
    int head = rem >> 5;                             // 0..31
    int i    = rem & 31;                             // freq index
    int s    = row & (S_ - 1);
    float* base = (blockIdx.y == 0 ? g_Q : g_K);
    float* p = base + ((long)(row * 32 + head) << 6) + 2 * i;
    float x1 = p[0], x2 = p[1];
    float c = g_cos[s * 32 + i], sn = g_sin[s * 32 + i];
    p[0] = x1 * c - x2 * sn;
    p[1] = x1 * sn + x2 * c;
}

// ---------------- fused dual-stream causal flash attention + diff + RMSnorm ----------------
// block = 128 threads, M=16 query rows, N=32 key rows per tile.
// thread t: query row qr = t>>3, lane group sub = t&7 (owns 4 key cols / 16 v-dims)
#define FM 16
#define FN 32

__global__ __launch_bounds__(128) void flash_kernel(const float* __restrict__ lnw) {
    __shared__ float sQ1[FM][72], sQ2[FM][72];
    __shared__ float sK1[FN][72], sK2[FN][72];
    __shared__ float sV[FN][128];
    __shared__ float sP1[FM][FN], sP2[FM][FN];

    int bid = blockIdx.x;
    int qt = bid & 127;            // S/FM
    int h  = (bid >> 7) & 15;
    int b  = bid >> 11;
    int tid = threadIdx.x;
    int qr = tid >> 3, sub = tid & 7;
    int q0 = qt * FM;
    int qglob = q0 + qr;

    // load Q tiles (both streams)
    for (int i = tid; i < FM * 16; i += 128) {
        int row = i >> 4, c4 = (i & 15) << 2;
        long base = ((long)((b * S_ + q0 + row) * 32 + 2 * h)) << 6;
        *(float4*)&sQ1[row][c4] = *(const float4*)&g_Q[base + c4];
        *(float4*)&sQ2[row][c4] = *(const float4*)&g_Q[base + 64 + c4];
    }

    float acc1[16], acc2[16];
    #pragma unroll
    for (int i = 0; i < 16; i++) { acc1[i] = 0.f; acc2[i] = 0.f; }
    float m1 = -1e30f, m2 = -1e30f, l1 = 0.f, l2 = 0.f;

    int nTiles = (q0 + FM - 1) / FN + 1;
    int d0 = sub << 4;   // this thread's 16 v-dims

    for (int t0 = 0; t0 < nTiles; t0++) {
        int n0 = t0 * FN;
        __syncthreads();   // previous-iter smem reads done (also covers Q load on t0=0)

        // load K tiles (both streams)
        for (int i = tid; i < FN * 16; i += 128) {
            int row = i >> 4, c4 = (i & 15) << 2;
            long base = ((long)((b * S_ + n0 + row) * 32 + 2 * h)) << 6;
            *(float4*)&sK1[row][c4] = *(const float4*)&g_K[base + c4];
            *(float4*)&sK2[row][c4] = *(const float4*)&g_K[base + 64 + c4];
        }
        // load V tile
        for (int i = tid; i < FN * 32; i += 128) {
            int row = i >> 5, c4 = (i & 31) << 2;
            *(float4*)&sV[row][c4] =
                *(const float4*)&g_V[(((long)(b * S_ + n0 + row) * 16 + h) << 7) + c4];
        }
        __syncthreads();

        // scores: each thread does 4 key cols per stream
        float s1v[4] = {0.f, 0.f, 0.f, 0.f};
        float s2v[4] = {0.f, 0.f, 0.f, 0.f};
        #pragma unroll 4
        for (int d = 0; d < 64; d += 4) {
            float4 q1 = *(float4*)&sQ1[qr][d];
            float4 q2 = *(float4*)&sQ2[qr][d];
            #pragma unroll
            for (int j = 0; j < 4; j++) {
                int kc = sub + (j << 3);
                float4 k1 = *(float4*)&sK1[kc][d];
                float4 k2 = *(float4*)&sK2[kc][d];
                s1v[j] += q1.x * k1.x + q1.y * k1.y + q1.z * k1.z + q1.w * k1.w;
                s2v[j] += q2.x * k2.x + q2.y * k2.y + q2.z * k2.z + q2.w * k2.w;
            }
        }
        float tmax1 = -1e30f, tmax2 = -1e30f;
        #pragma unroll
        for (int j = 0; j < 4; j++) {
            int kg = n0 + sub + (j << 3);
            bool ok = (kg <= qglob);
            s1v[j] = ok ? s1v[j] * 0.125f : -1e30f;
            s2v[j] = ok ? s2v[j] * 0.125f : -1e30f;
            tmax1 = fmaxf(tmax1, s1v[j]);
            tmax2 = fmaxf(tmax2, s2v[j]);
        }
        // reduce max over the 8-thread row group (lanes aligned to 8)
        #pragma unroll
        for (int w = 1; w < 8; w <<= 1) {
            tmax1 = fmaxf(tmax1, __shfl_xor_sync(0xffffffffu, tmax1, w));
            tmax2 = fmaxf(tmax2, __shfl_xor_sync(0xffffffffu, tmax2, w));
        }
        float nm1 = fmaxf(m1, tmax1);
        float nm2 = fmaxf(m2, tmax2);
        float c1 = __expf(m1 - nm1);
        float c2 = __expf(m2 - nm2);
        float ps1 = 0.f, ps2 = 0.f;
        #pragma unroll
        for (int j = 0; j < 4; j++) {
            int kc = sub + (j << 3);
            float p1 = __expf(s1v[j] - nm1);
            float p2 = __expf(s2v[j] - nm2);
            ps1 += p1; ps2 += p2;
            sP1[qr][kc] = p1;
            sP2[qr][kc] = p2;
        }
        #pragma unroll
        for (int w = 1; w < 8; w <<= 1) {
            ps1 += __shfl_xor_sync(0xffffffffu, ps1, w);
            ps2 += __shfl_xor_sync(0xffffffffu, ps2, w);
        }
        l1 = l1 * c1 + ps1;
        l2 = l2 * c2 + ps2;
        m1 = nm1; m2 = nm2;
        #pragma unroll
        for (int i = 0; i < 16; i++) { acc1[i] *= c1; acc2[i] *= c2; }

        __syncwarp();   // sP rows are produced & consumed within one warp

        // PV accumulate: 32 keys x 16 dims, both streams
        #pragma unroll 8
        for (int kc = 0; kc < FN; kc++) {
            float p1 = sP1[qr][kc];
            float p2 = sP2[qr][kc];
            #pragma unroll
            for (int dd = 0; dd < 16; dd += 4) {
                float4 v4 = *(float4*)&sV[kc][d0 + dd];
                acc1[dd + 0] += p1 * v4.x; acc1[dd + 1] += p1 * v4.y;
                acc1[dd + 2] += p1 * v4.z; acc1[dd + 3] += p1 * v4.w;
                acc2[dd + 0] += p2 * v4.x; acc2[dd + 1] += p2 * v4.y;
                acc2[dd + 2] += p2 * v4.z; acc2[dd + 3] += p2 * v4.w;
            }
        }
    }

    // epilogue: diff, RMS norm over 128 dims, ln_w, output scale
    float inv1 = 1.f / l1;
    float inv2 = 1.f / l2;
    float lam = g_lambda;
    float outv[16];
    float ss = 0.f;
    #pragma unroll
    for (int i = 0; i < 16; i++) {
        float a = acc1[i] * inv1 - lam * (acc2[i] * inv2);
        outv[i] = a;
        ss += a * a;
    }
    #pragma unroll
    for (int w = 1; w < 8; w <<= 1)
        ss += __shfl_xor_sync(0xffffffffu, ss, w);
    float rms = rsqrtf(ss * (1.f / 128.f) + 1e-5f);

    long obase = (((long)(b * S_ + qglob) * 16 + h) << 7) + d0;
    #pragma unroll
    for (int dd = 0; dd < 16; dd += 4) {
        float4 w4 = *(const float4*)&lnw[d0 + dd];
        float4 o;
        o.x = outv[dd + 0] * rms * w4.x * OUT_SCALE_F;
        o.y = outv[dd + 1] * rms * w4.y * OUT_SCALE_F;
        o.z = outv[dd + 2] * rms * w4.z * OUT_SCALE_F;
        o.w = outv[dd + 3] * rms * w4.w * OUT_SCALE_F;
        *(float4*)&g_A[obase + dd] = o;
    }
}

// ---------------- launch ----------------
extern "C" void kernel_launch(void* const* d_in, const int* in_sizes, int n_in,
                              void* d_out, int out_size) {
    const float* x   = (const float*)d_in[0];
    const float* Wq  = (const float*)d_in[1];
    const float* Wk  = (const float*)d_in[2];
    const float* Wv  = (const float*)d_in[3];
    const float* Wo  = (const float*)d_in[4];
    const float* lq1 = (const float*)d_in[5];
    const float* lk1 = (const float*)d_in[6];
    const float* lq2 = (const float*)d_in[7];
    const float* lk2 = (const float*)d_in[8];
    const float* lnw = (const float*)d_in[9];
    float* out = (float*)d_out;

    float *Q, *K, *V, *A;
    cudaGetSymbolAddress((void**)&Q, g_Q);
    cudaGetSymbolAddress((void**)&K, g_K);
    cudaGetSymbolAddress((void**)&V, g_V);
    cudaGetSymbolAddress((void**)&A, g_A);

    prep_tables_kernel<<<S_, 32>>>();
    prep_lambda_kernel<<<1, 64>>>(lq1, lk1, lq2, lk2);

    dim3 gg(E_ / 128, ROWS_ / 128);
    sgemm_kernel<<<gg, 256>>>(x, Wq, Q, ROWS_, E_, E_);
    sgemm_kernel<<<gg, 256>>>(x, Wk, K, ROWS_, E_, E_);
    sgemm_kernel<<<gg, 256>>>(x, Wv, V, ROWS_, E_, E_);

    dim3 rg((ROWS_ * 1024) / 256, 2);
    rope_kernel<<<rg, 256>>>();

    flash_kernel<<<B_ * H_ * (S_ / FM), 128>>>(lnw);

    sgemm_kernel<<<gg, 256>>>(A, Wo, out, ROWS_, E_, E_);
}

// round 4
// speedup vs baseline: 1.4878x; 1.4878x over previous
#include <cuda_runtime.h>
#include <cuda_bf16.h>
#include <cstdint>

#define B_ 2
#define S_ 2048
#define E_ 2048
#define H_ 16
#define HD_ 64
#define ROWS_ (B_ * S_)          // 4096
#define LAMBDA_INIT_F 0.783605766532f
#define OUT_SCALE_F   0.216394233468f   // 1 - LAMBDA_INIT

// ---------------- scratch (device globals; no allocations) ----------------
__device__ float g_Q[(size_t)ROWS_ * E_];     // [B,S,2H,HD] fp32 (pre-rope)
__device__ float g_K[(size_t)ROWS_ * E_];
__device__ float g_V[(size_t)ROWS_ * E_];     // [B,S,H,2HD] fp32
__device__ float g_A[(size_t)ROWS_ * E_];     // attention output pre-Wo (fp32)
__device__ __nv_bfloat16 g_Qbf[2][(size_t)ROWS_ * E_];  // [half][(row*32+head)*64+d] post-rope
__device__ __nv_bfloat16 g_Kbf[2][(size_t)ROWS_ * E_];
__device__ __nv_bfloat16 g_Vbf[2][(size_t)ROWS_ * E_];  // [half][(row*16+h)*128+d]
__device__ float g_cos[S_ * 32];
__device__ float g_sin[S_ * 32];
__device__ float g_lambda;

// ---------------- small helpers ----------------
__device__ __forceinline__ uint32_t smem_u32(const void* p) {
    uint32_t a;
    asm("{ .reg .u64 t; cvta.to.shared.u64 t, %1; cvt.u32.u64 %0, t; }" : "=r"(a) : "l"(p));
    return a;
}
#define CP_ASYNC16(dst, src) \
    asm volatile("cp.async.cg.shared.global [%0], [%1], 16;" :: "r"(dst), "l"(src))
#define CP_ASYNC_COMMIT() asm volatile("cp.async.commit_group;" ::: "memory")
#define CP_ASYNC_WAIT(n)  asm volatile("cp.async.wait_group %0;" :: "n"(n) : "memory")

#define LDSM_X4(r0, r1, r2, r3, addr) \
    asm volatile("ldmatrix.sync.aligned.m8n8.x4.shared.b16 {%0,%1,%2,%3}, [%4];" \
                 : "=r"(r0), "=r"(r1), "=r"(r2), "=r"(r3) : "r"(addr))
#define LDSM_X4_T(r0, r1, r2, r3, addr) \
    asm volatile("ldmatrix.sync.aligned.m8n8.x4.trans.shared.b16 {%0,%1,%2,%3}, [%4];" \
                 : "=r"(r0), "=r"(r1), "=r"(r2), "=r"(r3) : "r"(addr))

__device__ __forceinline__ void mma_bf16(float* c, const uint32_t* a, uint32_t b0, uint32_t b1) {
    asm volatile(
        "mma.sync.aligned.m16n8k16.row.col.f32.bf16.bf16.f32 "
        "{%0,%1,%2,%3}, {%4,%5,%6,%7}, {%8,%9}, {%0,%1,%2,%3};"
        : "+f"(c[0]), "+f"(c[1]), "+f"(c[2]), "+f"(c[3])
        : "r"(a[0]), "r"(a[1]), "r"(a[2]), "r"(a[3]), "r"(b0), "r"(b1));
}

// split two floats into packed bf16 hi pair + lo pair
__device__ __forceinline__ void split2(float x, float y, uint32_t& hi, uint32_t& lo) {
    __nv_bfloat16 hx = __float2bfloat16(x), hy = __float2bfloat16(y);
    float rx = x - __bfloat162float(hx), ry = y - __bfloat162float(hy);
    __nv_bfloat16 lx = __float2bfloat16(rx), ly = __float2bfloat16(ry);
    uint16_t uhx = *(uint16_t*)&hx, uhy = *(uint16_t*)&hy;
    uint16_t ulx = *(uint16_t*)&lx, uly = *(uint16_t*)&ly;
    hi = (uint32_t)uhx | ((uint32_t)uhy << 16);
    lo = (uint32_t)ulx | ((uint32_t)uly << 16);
}

// ---------------- prep kernels ----------------
__global__ void prep_tables_kernel() {
    int t = blockIdx.x;
    int i = threadIdx.x;
    float inv = (float)pow(10000.0, -(double)i / 32.0);
    float f = (float)t * inv;
    g_cos[t * 32 + i] = cosf(f);
    g_sin[t * 32 + i] = sinf(f);
}

__global__ void prep_lambda_kernel(const float* __restrict__ lq1, const float* __restrict__ lk1,
                                   const float* __restrict__ lq2, const float* __restrict__ lk2) {
    __shared__ float s1[64], s2[64];
    int i = threadIdx.x;
    s1[i] = lq1[i] * lk1[i];
    s2[i] = lq2[i] * lk2[i];
    __syncthreads();
    if (i == 0) {
        float a = 0.f, b = 0.f;
        for (int j = 0; j < 64; j++) { a += s1[j]; b += s2[j]; }
        g_lambda = expf(a) - expf(b) + LAMBDA_INIT_F;
    }
}

// ---------------- SGEMM: C[M,N] = A[M,K] @ B[K,N], fp32 (proven @ roofline) ----------------
__global__ __launch_bounds__(256) void sgemm_kernel(
    const float* __restrict__ A, const float* __restrict__ B, float* __restrict__ C,
    int M, int N, int K)
{
    __shared__ float As[8][128];
    __shared__ float Bs[8][128];
    int tid = threadIdx.x;
    int brow = blockIdx.y * 128;
    int bcol = blockIdx.x * 128;

    int arow = tid >> 1;
    int acol = (tid & 1) << 2;
    int brl  = tid >> 5;
    int bcl  = (tid & 31) << 2;

    int trow = (tid >> 4) << 3;
    int tcol = (tid & 15) << 3;

    float acc[8][8];
    #pragma unroll
    for (int i = 0; i < 8; i++)
        #pragma unroll
        for (int j = 0; j < 8; j++) acc[i][j] = 0.f;

    for (int k0 = 0; k0 < K; k0 += 8) {
        float4 a4 = *(const float4*)&A[(long)(brow + arow) * K + k0 + acol];
        As[acol + 0][arow] = a4.x;
        As[acol + 1][arow] = a4.y;
        As[acol + 2][arow] = a4.z;
        As[acol + 3][arow] = a4.w;
        *(float4*)&Bs[brl][bcl] = *(const float4*)&B[(long)(k0 + brl) * N + bcol + bcl];
        __syncthreads();

        #pragma unroll
        for (int kk = 0; kk < 8; kk++) {
            float4 a0 = *(float4*)&As[kk][trow];
            float4 a1 = *(float4*)&As[kk][trow + 4];
            float4 b0 = *(float4*)&Bs[kk][tcol];
            float4 b1 = *(float4*)&Bs[kk][tcol + 4];
            float ar[8] = {a0.x, a0.y, a0.z, a0.w, a1.x, a1.y, a1.z, a1.w};
            float br[8] = {b0.x, b0.y, b0.z, b0.w, b1.x, b1.y, b1.z, b1.w};
            #pragma unroll
            for (int i = 0; i < 8; i++)
                #pragma unroll
                for (int j = 0; j < 8; j++)
                    acc[i][j] += ar[i] * br[j];
        }
        __syncthreads();
    }

    #pragma unroll
    for (int i = 0; i < 8; i++) {
        #pragma unroll
        for (int j = 0; j < 8; j += 4) {
            float4 v = make_float4(acc[i][j], acc[i][j + 1], acc[i][j + 2], acc[i][j + 3]);
            *(float4*)&C[(long)(brow + trow + i) * N + bcol + tcol + j] = v;
        }
    }
}

// ---------------- RoPE (interleaved) + split to bf16 hi/lo ----------------
// grid: (ROWS_*1024/256, 2); y=0 -> Q, y=1 -> K
__global__ void rope_conv_kernel() {
    int idx = blockIdx.x * 256 + threadIdx.x;
    int row = idx >> 10;
    int rem = idx & 1023;
    int head = rem >> 5;
    int i = rem & 31;
    int s = row & (S_ - 1);
    const float* basef = (blockIdx.y == 0 ? g_Q : g_K);
    __nv_bfloat16* dh = (blockIdx.y == 0 ? g_Qbf[0] : g_Kbf[0]);
    __nv_bfloat16* dl = (blockIdx.y == 0 ? g_Qbf[1] : g_Kbf[1]);
    size_t off = (((size_t)row * 32 + head) << 6) + 2 * i;
    float x1 = basef[off], x2 = basef[off + 1];
    float c = g_cos[s * 32 + i], sn = g_sin[s * 32 + i];
    float o1 = x1 * c - x2 * sn;
    float o2 = x1 * sn + x2 * c;
    __nv_bfloat16 h1 = __float2bfloat16(o1), h2 = __float2bfloat16(o2);
    dh[off] = h1;
    dh[off + 1] = h2;
    dl[off] = __float2bfloat16(o1 - __bfloat162float(h1));
    dl[off + 1] = __float2bfloat16(o2 - __bfloat162float(h2));
}

__global__ void vsplit_kernel() {
    size_t i = (size_t)blockIdx.x * 256 + threadIdx.x;
    float v = g_V[i];
    __nv_bfloat16 h = __float2bfloat16(v);
    g_Vbf[0][i] = h;
    g_Vbf[1][i] = __float2bfloat16(v - __bfloat162float(h));
}

// ---------------- flash attention via mma.sync (bf16 3-term split) ----------------
// CTA: 256 threads (8 warps). 64 query rows per CTA, 64 keys per tile.
// warps 0-3: stream 1, warps 4-7: stream 2 (same query rows, 16 each).
// smem per buffer: K: 4 regions (stream x half) 64x72 halves (stride 144B) = 36864B
//                  V: 2 regions (half) 64x136 halves (stride 272B)         = 34816B
// double buffered: 2 * 71680 = 143360B dynamic smem.
#define FB_BYTES 71680
#define KREG(buf, ss)  ((buf) * FB_BYTES + (ss) * 9216)
#define VREG(buf, hf)  ((buf) * FB_BYTES + 36864 + (hf) * 17408)

__global__ __launch_bounds__(256) void flash_mma_kernel(const float* __restrict__ lnw) {
    extern __shared__ char smem[];
    uint32_t sb = smem_u32(smem);
    __shared__ float sLn[128];

    int tid = threadIdx.x, lane = tid & 31, wid = tid >> 5;
    int stream = wid >> 2, qw = wid & 3;
    int qt = 31 - blockIdx.x;           // heavy tiles first
    int h = blockIdx.y, b = blockIdx.z;
    int q0 = qt * 64;
    int bS = b * S_;
    if (tid < 128) sLn[tid] = lnw[tid];

    // ---- stage Q (rows q0..q0+63, both streams/halves) into buffer 1's K region ----
    for (int i = tid; i < 2048; i += 256) {
        int ss = i >> 9, r = (i >> 3) & 63, c = i & 7;
        uint32_t dst = sb + KREG(1, ss) + r * 144 + c * 16;
        const __nv_bfloat16* src =
            &g_Qbf[ss & 1][(((size_t)(bS + q0 + r) * 32 + 2 * h + (ss >> 1)) << 6) + c * 8];
        CP_ASYNC16(dst, src);
    }
    CP_ASYNC_COMMIT();
    CP_ASYNC_WAIT(0);
    __syncthreads();

    // ---- Q fragments (4 k-chunks of m16k16, hi & lo) ----
    uint32_t qh[4][4], ql[4][4];
    {
        int row = qw * 16 + (lane & 7) + ((lane >> 3) & 1) * 8;
        uint32_t boff = ((lane >> 4) & 1) * 16;
        uint32_t bh_ = sb + KREG(1, stream * 2 + 0) + row * 144 + boff;
        uint32_t bl_ = sb + KREG(1, stream * 2 + 1) + row * 144 + boff;
        #pragma unroll
        for (int kc = 0; kc < 4; kc++) {
            LDSM_X4(qh[kc][0], qh[kc][1], qh[kc][2], qh[kc][3], bh_ + kc * 32);
            LDSM_X4(ql[kc][0], ql[kc][1], ql[kc][2], ql[kc][3], bl_ + kc * 32);
        }
    }
    __syncthreads();

    // ---- K/V tile loader ----
    auto load_tile = [&](int kt) {
        int n0 = kt * 64, buf = kt & 1;
        for (int i = tid; i < 4096; i += 256) {
            uint32_t dst;
            const __nv_bfloat16* src;
            if (i < 2048) {
                int ss = i >> 9, r = (i >> 3) & 63, c = i & 7;
                dst = sb + KREG(buf, ss) + r * 144 + c * 16;
                src = &g_Kbf[ss & 1][(((size_t)(bS + n0 + r) * 32 + 2 * h + (ss >> 1)) << 6) + c * 8];
            } else {
                int j = i - 2048;
                int hf = j >> 10, r = (j >> 4) & 63, c = j & 15;
                dst = sb + VREG(buf, hf) + r * 272 + c * 16;
                src = &g_Vbf[hf][(((size_t)(bS + n0 + r) * 16 + h) << 7) + c * 8];
            }
            CP_ASYNC16(dst, src);
        }
        CP_ASYNC_COMMIT();
    };

    float out[16][4];
    #pragma unroll
    for (int i = 0; i < 16; i++)
        #pragma unroll
        for (int e = 0; e < 4; e++) out[i][e] = 0.f;
    float m0 = -1e30f, m1 = -1e30f, l0 = 0.f, l1 = 0.f;

    load_tile(0);

    for (int kt = 0; kt <= qt; kt++) {
        int buf = kt & 1;
        __syncthreads();                 // everyone done with buffer (kt+1)&1
        if (kt < qt) { load_tile(kt + 1); CP_ASYNC_WAIT(1); }
        else         { CP_ASYNC_WAIT(0); }
        __syncthreads();

        // ---- scores S = Q K^T (3-term split) ----
        float sacc[8][4];
        #pragma unroll
        for (int nt = 0; nt < 8; nt++)
            #pragma unroll
            for (int e = 0; e < 4; e++) sacc[nt][e] = 0.f;

        uint32_t kbh = sb + KREG(buf, stream * 2 + 0);
        uint32_t kbl = sb + KREG(buf, stream * 2 + 1);
        int krow = lane & 7;
        uint32_t kboff = (lane >> 3) * 16;  // 0,16,32,48

        #pragma unroll
        for (int nt = 0; nt < 8; nt++) {
            uint32_t bh[2][4], bl[2][4];
            uint32_t rowa = (nt * 8 + krow) * 144 + kboff;
            LDSM_X4(bh[0][0], bh[0][1], bh[0][2], bh[0][3], kbh + rowa);
            LDSM_X4(bh[1][0], bh[1][1], bh[1][2], bh[1][3], kbh + rowa + 64);
            LDSM_X4(bl[0][0], bl[0][1], bl[0][2], bl[0][3], kbl + rowa);
            LDSM_X4(bl[1][0], bl[1][1], bl[1][2], bl[1][3], kbl + rowa + 64);
            #pragma unroll
            for (int kc = 0; kc < 4; kc++) {
                uint32_t b0h = bh[kc >> 1][2 * (kc & 1)], b1h = bh[kc >> 1][2 * (kc & 1) + 1];
                uint32_t b0l = bl[kc >> 1][2 * (kc & 1)], b1l = bl[kc >> 1][2 * (kc & 1) + 1];
                mma_bf16(sacc[nt], qh[kc], b0h, b1h);
                mma_bf16(sacc[nt], ql[kc], b0h, b1h);
                mma_bf16(sacc[nt], qh[kc], b0l, b1l);
            }
        }

        // ---- online softmax (2 rows per thread) ----
        bool diag = (kt == qt);
        int rlo0 = qw * 16 + (lane >> 2);    // tile-local row for e0,e1
        float rm0 = -1e30f, rm1 = -1e30f;
        #pragma unroll
        for (int nt = 0; nt < 8; nt++) {
            #pragma unroll
            for (int e = 0; e < 4; e++) {
                float s = sacc[nt][e] * 0.125f;
                if (diag) {
                    int colL = nt * 8 + 2 * (lane & 3) + (e & 1);
                    int rowL = rlo0 + ((e >> 1) << 3);
                    if (colL > rowL) s = -1e30f;
                }
                sacc[nt][e] = s;
                if (e < 2) rm0 = fmaxf(rm0, s); else rm1 = fmaxf(rm1, s);
            }
        }
        #pragma unroll
        for (int w = 1; w < 4; w <<= 1) {
            rm0 = fmaxf(rm0, __shfl_xor_sync(0xffffffffu, rm0, w));
            rm1 = fmaxf(rm1, __shfl_xor_sync(0xffffffffu, rm1, w));
        }
        float nm0 = fmaxf(m0, rm0), nm1 = fmaxf(m1, rm1);
        float c0 = __expf(m0 - nm0), c1 = __expf(m1 - nm1);
        float ps0 = 0.f, ps1 = 0.f;
        #pragma unroll
        for (int nt = 0; nt < 8; nt++) {
            float p0 = __expf(sacc[nt][0] - nm0);
            float p1 = __expf(sacc[nt][1] - nm0);
            float p2 = __expf(sacc[nt][2] - nm1);
            float p3 = __expf(sacc[nt][3] - nm1);
            sacc[nt][0] = p0; sacc[nt][1] = p1; sacc[nt][2] = p2; sacc[nt][3] = p3;
            ps0 += p0 + p1; ps1 += p2 + p3;
        }
        #pragma unroll
        for (int w = 1; w < 4; w <<= 1) {
            ps0 += __shfl_xor_sync(0xffffffffu, ps0, w);
            ps1 += __shfl_xor_sync(0xffffffffu, ps1, w);
        }
        l0 = l0 * c0 + ps0;
        l1 = l1 * c1 + ps1;
        m0 = nm0; m1 = nm1;
        #pragma unroll
        for (int nt = 0; nt < 16; nt++) {
            out[nt][0] *= c0; out[nt][1] *= c0;
            out[nt][2] *= c1; out[nt][3] *= c1;
        }

        // ---- PV (3-term split) ----
        uint32_t vbh = sb + VREG(buf, 0);
        uint32_t vbl = sb + VREG(buf, 1);
        int vrow = (lane & 7) + ((lane >> 3) & 1) * 8;
        uint32_t vboff = ((lane >> 4) & 1) * 16;
        #pragma unroll
        for (int kc2 = 0; kc2 < 4; kc2++) {
            uint32_t pah[4], pal[4];
            split2(sacc[2 * kc2][0], sacc[2 * kc2][1], pah[0], pal[0]);
            split2(sacc[2 * kc2][2], sacc[2 * kc2][3], pah[1], pal[1]);
            split2(sacc[2 * kc2 + 1][0], sacc[2 * kc2 + 1][1], pah[2], pal[2]);
            split2(sacc[2 * kc2 + 1][2], sacc[2 * kc2 + 1][3], pah[3], pal[3]);
            uint32_t vra = (kc2 * 16 + vrow) * 272 + vboff;
            #pragma unroll
            for (int dp = 0; dp < 8; dp++) {
                uint32_t vh[4], vl[4];
                LDSM_X4_T(vh[0], vh[1], vh[2], vh[3], vbh + vra + dp * 32);
                LDSM_X4_T(vl[0], vl[1], vl[2], vl[3], vbl + vra + dp * 32);
                mma_bf16(out[2 * dp], pah, vh[0], vh[1]);
                mma_bf16(out[2 * dp], pal, vh[0], vh[1]);
                mma_bf16(out[2 * dp], pah, vl[0], vl[1]);
                mma_bf16(out[2 * dp + 1], pah, vh[2], vh[3]);
                mma_bf16(out[2 * dp + 1], pal, vh[2], vh[3]);
                mma_bf16(out[2 * dp + 1], pah, vl[2], vl[3]);
            }
        }
    }

    // ---- epilogue: diff across streams, RMS norm, write g_A ----
    float inv0 = 1.f / l0, inv1 = 1.f / l1;
    int r0 = qw * 16 + (lane >> 2);
    float* sX = (float*)smem;            // 64 x 132 fp32, fits in buffer 0's K region + more
    __syncthreads();
    if (stream == 1) {
        #pragma unroll
        for (int nt = 0; nt < 16; nt++) {
            int col = nt * 8 + 2 * (lane & 3);
            sX[r0 * 132 + col]           = out[nt][0] * inv0;
            sX[r0 * 132 + col + 1]       = out[nt][1] * inv0;
            sX[(r0 + 8) * 132 + col]     = out[nt][2] * inv1;
            sX[(r0 + 8) * 132 + col + 1] = out[nt][3] * inv1;
        }
    }
    __syncthreads();
    if (stream == 0) {
        float lam = g_lambda;
        float ss0 = 0.f, ss1 = 0.f;
        #pragma unroll
        for (int nt = 0; nt < 16; nt++) {
            int col = nt * 8 + 2 * (lane & 3);
            out[nt][0] = out[nt][0] * inv0 - lam * sX[r0 * 132 + col];
            out[nt][1] = out[nt][1] * inv0 - lam * sX[r0 * 132 + col + 1];
            out[nt][2] = out[nt][2] * inv1 - lam * sX[(r0 + 8) * 132 + col];
            out[nt][3] = out[nt][3] * inv1 - lam * sX[(r0 + 8) * 132 + col + 1];
            ss0 += out[nt][0] * out[nt][0] + out[nt][1] * out[nt][1];
            ss1 += out[nt][2] * out[nt][2] + out[nt][3] * out[nt][3];
        }
        #pragma unroll
        for (int w = 1; w < 4; w <<= 1) {
            ss0 += __shfl_xor_sync(0xffffffffu, ss0, w);
            ss1 += __shfl_xor_sync(0xffffffffu, ss1, w);
        }
        float rms0 = rsqrtf(ss0 * (1.f / 128.f) + 1e-5f);
        float rms1 = rsqrtf(ss1 * (1.f / 128.f) + 1e-5f);
        #pragma unroll
        for (int nt = 0; nt < 16; nt++) {
            int col = nt * 8 + 2 * (lane & 3);
            size_t ga = ((size_t)(bS + q0 + r0)) * 2048 + h * 128 + col;
            size_t gb = ((size_t)(bS + q0 + r0 + 8)) * 2048 + h * 128 + col;
            g_A[ga]     = out[nt][0] * rms0 * sLn[col] * OUT_SCALE_F;
            g_A[ga + 1] = out[nt][1] * rms0 * sLn[col + 1] * OUT_SCALE_F;
            g_A[gb]     = out[nt][2] * rms1 * sLn[col] * OUT_SCALE_F;
            g_A[gb + 1] = out[nt][3] * rms1 * sLn[col + 1] * OUT_SCALE_F;
        }
    }
}

// ---------------- launch ----------------
extern "C" void kernel_launch(void* const* d_in, const int* in_sizes, int n_in,
                              void* d_out, int out_size) {
    const float* x   = (const float*)d_in[0];
    const float* Wq  = (const float*)d_in[1];
    const float* Wk  = (const float*)d_in[2];
    const float* Wv  = (const float*)d_in[3];
    const float* Wo  = (const float*)d_in[4];
    const float* lq1 = (const float*)d_in[5];
    const float* lk1 = (const float*)d_in[6];
    const float* lq2 = (const float*)d_in[7];
    const float* lk2 = (const float*)d_in[8];
    const float* lnw = (const float*)d_in[9];
    float* out = (float*)d_out;

    float *Q, *K, *V, *A;
    cudaGetSymbolAddress((void**)&Q, g_Q);
    cudaGetSymbolAddress((void**)&K, g_K);
    cudaGetSymbolAddress((void**)&V, g_V);
    cudaGetSymbolAddress((void**)&A, g_A);

    cudaFuncSetAttribute(flash_mma_kernel, cudaFuncAttributeMaxDynamicSharedMemorySize,
                         2 * FB_BYTES);

    prep_tables_kernel<<<S_, 32>>>();
    prep_lambda_kernel<<<1, 64>>>(lq1, lk1, lq2, lk2);

    dim3 gg(E_ / 128, ROWS_ / 128);
    sgemm_kernel<<<gg, 256>>>(x, Wq, Q, ROWS_, E_, E_);
    sgemm_kernel<<<gg, 256>>>(x, Wk, K, ROWS_, E_, E_);
    sgemm_kernel<<<gg, 256>>>(x, Wv, V, ROWS_, E_, E_);

    dim3 rg((ROWS_ * 1024) / 256, 2);
    rope_conv_kernel<<<rg, 256>>>();
    vsplit_kernel<<<((size_t)ROWS_ * E_) / 256, 256>>>();

    dim3 fg(32, 16, 2);
    flash_mma_kernel<<<fg, 256, 2 * FB_BYTES>>>(lnw);

    sgemm_kernel<<<gg, 256>>>(A, Wo, out, ROWS_, E_, E_);
}

// round 5
// speedup vs baseline: 4.3944x; 2.9537x over previous
#include <cuda_runtime.h>
#include <cuda_bf16.h>
#include <cstdint>

#define B_ 2
#define S_ 2048
#define E_ 2048
#define H_ 16
#define HD_ 64
#define ROWS_ (B_ * S_)          // 4096
#define LAMBDA_INIT_F 0.783605766532f
#define OUT_SCALE_F   0.216394233468f   // 1 - LAMBDA_INIT

// ---------------- scratch (device globals; no allocations) ----------------
__device__ float g_Q[(size_t)ROWS_ * E_];     // [B,S,2H,HD] fp32 (pre-rope)
__device__ float g_K[(size_t)ROWS_ * E_];
__device__ float g_V[(size_t)ROWS_ * E_];     // [B,S,H,2HD] fp32
__device__ __nv_bfloat16 g_xhi[(size_t)ROWS_ * E_];
__device__ __nv_bfloat16 g_xlo[(size_t)ROWS_ * E_];
__device__ __nv_bfloat16 g_Ahi[(size_t)ROWS_ * E_];   // flash output split
__device__ __nv_bfloat16 g_Alo[(size_t)ROWS_ * E_];
__device__ __nv_bfloat16 g_Wt_hi[4][(size_t)E_ * E_]; // transposed weights [n][k]: q,k,v,o
__device__ __nv_bfloat16 g_Wt_lo[4][(size_t)E_ * E_];
__device__ __nv_bfloat16 g_Qbf[2][(size_t)ROWS_ * E_];  // [half][(row*32+head)*64+d] post-rope
__device__ __nv_bfloat16 g_Kbf[2][(size_t)ROWS_ * E_];
__device__ __nv_bfloat16 g_Vbf[2][(size_t)ROWS_ * E_];  // [half][(row*16+h)*128+d]
__device__ float g_cos[S_ * 32];
__device__ float g_sin[S_ * 32];
__device__ float g_lambda;

// ---------------- small helpers ----------------
__device__ __forceinline__ uint32_t smem_u32(const void* p) {
    uint32_t a;
    asm("{ .reg .u64 t; cvta.to.shared.u64 t, %1; cvt.u32.u64 %0, t; }" : "=r"(a) : "l"(p));
    return a;
}
#define CP_ASYNC16(dst, src) \
    asm volatile("cp.async.cg.shared.global [%0], [%1], 16;" :: "r"(dst), "l"(src))
#define CP_ASYNC_COMMIT() asm volatile("cp.async.commit_group;" ::: "memory")
#define CP_ASYNC_WAIT(n)  asm volatile("cp.async.wait_group %0;" :: "n"(n) : "memory")

#define LDSM_X4(r0, r1, r2, r3, addr) \
    asm volatile("ldmatrix.sync.aligned.m8n8.x4.shared.b16 {%0,%1,%2,%3}, [%4];" \
                 : "=r"(r0), "=r"(r1), "=r"(r2), "=r"(r3) : "r"(addr))
#define LDSM_X4_T(r0, r1, r2, r3, addr) \
    asm volatile("ldmatrix.sync.aligned.m8n8.x4.trans.shared.b16 {%0,%1,%2,%3}, [%4];" \
                 : "=r"(r0), "=r"(r1), "=r"(r2), "=r"(r3) : "r"(addr))

__device__ __forceinline__ void mma_bf16(float* c, const uint32_t* a, uint32_t b0, uint32_t b1) {
    asm volatile(
        "mma.sync.aligned.m16n8k16.row.col.f32.bf16.bf16.f32 "
        "{%0,%1,%2,%3}, {%4,%5,%6,%7}, {%8,%9}, {%0,%1,%2,%3};"
        : "+f"(c[0]), "+f"(c[1]), "+f"(c[2]), "+f"(c[3])
        : "r"(a[0]), "r"(a[1]), "r"(a[2]), "r"(a[3]), "r"(b0), "r"(b1));
}

// split two floats into packed bf16 hi pair + lo pair
__device__ __forceinline__ void split2(float x, float y, uint32_t& hi, uint32_t& lo) {
    __nv_bfloat16 hx = __float2bfloat16(x), hy = __float2bfloat16(y);
    float rx = x - __bfloat162float(hx), ry = y - __bfloat162float(hy);
    __nv_bfloat16 lx = __float2bfloat16(rx), ly = __float2bfloat16(ry);
    uint16_t uhx = *(uint16_t*)&hx, uhy = *(uint16_t*)&hy;
    uint16_t ulx = *(uint16_t*)&lx, uly = *(uint16_t*)&ly;
    hi = (uint32_t)uhx | ((uint32_t)uhy << 16);
    lo = (uint32_t)ulx | ((uint32_t)uly << 16);
}

// ---------------- prep kernels ----------------
__global__ void prep_tables_kernel() {
    int t = blockIdx.x;
    int i = threadIdx.x;
    float inv = (float)pow(10000.0, -(double)i / 32.0);
    float f = (float)t * inv;
    g_cos[t * 32 + i] = cosf(f);
    g_sin[t * 32 + i] = sinf(f);
}

__global__ void prep_lambda_kernel(const float* __restrict__ lq1, const float* __restrict__ lk1,
                                   const float* __restrict__ lq2, const float* __restrict__ lk2) {
    __shared__ float s1[64], s2[64];
    int i = threadIdx.x;
    s1[i] = lq1[i] * lk1[i];
    s2[i] = lq2[i] * lk2[i];
    __syncthreads();
    if (i == 0) {
        float a = 0.f, b = 0.f;
        for (int j = 0; j < 64; j++) { a += s1[j]; b += s2[j]; }
        g_lambda = expf(a) - expf(b) + LAMBDA_INIT_F;
    }
}

// ---------------- split x into bf16 hi/lo ----------------
__global__ void split_x_kernel(const float* __restrict__ x) {
    size_t i = (size_t)blockIdx.x * 256 + threadIdx.x;
    float v = x[i];
    __nv_bfloat16 h = __float2bfloat16(v);
    g_xhi[i] = h;
    g_xlo[i] = __float2bfloat16(v - __bfloat162float(h));
}

// ---------------- transpose + split W: [k][n] f32 -> [n][k] bf16 hi/lo ----------------
__global__ void transpose_split_kernel(const float* __restrict__ W,
                                       __nv_bfloat16* __restrict__ hi,
                                       __nv_bfloat16* __restrict__ lo) {
    __shared__ float t[32][33];
    int k0 = blockIdx.x * 32, n0 = blockIdx.y * 32;
    int tx = threadIdx.x, ty = threadIdx.y;   // 32 x 8
    #pragma unroll
    for (int j = 0; j < 32; j += 8)
        t[ty + j][tx] = W[(size_t)(k0 + ty + j) * E_ + n0 + tx];
    __syncthreads();
    #pragma unroll
    for (int j = 0; j < 32; j += 8) {
        float v = t[tx][ty + j];
        size_t o = (size_t)(n0 + ty + j) * E_ + k0 + tx;
        __nv_bfloat16 h = __float2bfloat16(v);
        hi[o] = h;
        lo[o] = __float2bfloat16(v - __bfloat162float(h));
    }
}

// ---------------- mma.sync bf16 3-term GEMM: C[4096,2048] = A @ B^T ----------------
// A hi/lo [m][k], B hi/lo [n][k]. Tile BM=128 BN=128 BK=32, 8 warps (4m x 2n),
// warp tile m32 n64. Padded smem rows: 32 halves + 8 pad = 80B stride.
#define GS_BYTES 40960   // per stage: Ahi 10240 | Alo 10240 | Bhi 10240 | Blo 10240

__global__ __launch_bounds__(256, 1) void mma_gemm_kernel(
    const __nv_bfloat16* __restrict__ Ahi, const __nv_bfloat16* __restrict__ Alo,
    const __nv_bfloat16* __restrict__ Bhi, const __nv_bfloat16* __restrict__ Blo,
    float* __restrict__ C)
{
    extern __shared__ char smem[];
    uint32_t sb = smem_u32(smem);
    int tid = threadIdx.x, lane = tid & 31, wid = tid >> 5;
    int mw = wid >> 1, nw = wid & 1;
    int m0 = blockIdx.y * 128, n0 = blockIdx.x * 128;

    auto load_stage = [&](int it) {
        int s = it & 1;
        int k0 = it * 32;
        uint32_t st = sb + s * GS_BYTES;
        #pragma unroll
        for (int c = tid; c < 2048; c += 256) {
            int mat = c >> 10;            // 0=A, 1=B
            int cc = c & 1023;
            int p = cc >> 9;              // 0=hi, 1=lo
            int r = (cc >> 2) & 127;
            int ch = cc & 3;
            const __nv_bfloat16* src =
                (mat ? (p ? Blo : Bhi) + (size_t)(n0 + r) * 2048
                     : (p ? Alo : Ahi) + (size_t)(m0 + r) * 2048) + k0 + ch * 8;
            uint32_t dst = st + mat * 20480 + p * 10240 + r * 80 + ch * 16;
            CP_ASYNC16(dst, src);
        }
        CP_ASYNC_COMMIT();
    };

    float acc[2][8][4];
    #pragma unroll
    for (int m = 0; m < 2; m++)
        #pragma unroll
        for (int n = 0; n < 8; n++)
            #pragma unroll
            for (int e = 0; e < 4; e++) acc[m][n][e] = 0.f;

    load_stage(0);

    int krow = lane & 7;
    uint32_t kboff = (lane >> 3) * 16;                 // covers k32 per x4
    int arow = (lane & 7) + ((lane >> 3) & 1) * 8;
    uint32_t aboff = ((lane >> 4) & 1) * 16;

    for (int it = 0; it < 64; it++) {
        int s = it & 1;
        __syncthreads();
        if (it + 1 < 64) { load_stage(it + 1); CP_ASYNC_WAIT(1); }
        else             { CP_ASYNC_WAIT(0); }
        __syncthreads();

        uint32_t sA = sb + s * GS_BYTES;
        uint32_t sB = sA + 20480;

        uint32_t bh[8][4], bl[8][4];
        #pragma unroll
        for (int n = 0; n < 8; n++) {
            uint32_t ra = (uint32_t)(nw * 64 + n * 8 + krow) * 80 + kboff;
            LDSM_X4(bh[n][0], bh[n][1], bh[n][2], bh[n][3], sB + ra);
            LDSM_X4(bl[n][0], bl[n][1], bl[n][2], bl[n][3], sB + 10240 + ra);
        }

        #pragma unroll
        for (int kc = 0; kc < 2; kc++) {
            uint32_t ah[2][4], al[2][4];
            #pragma unroll
            for (int m = 0; m < 2; m++) {
                uint32_t ra = (uint32_t)(mw * 32 + m * 16 + arow) * 80 + aboff + kc * 32;
                LDSM_X4(ah[m][0], ah[m][1], ah[m][2], ah[m][3], sA + ra);
                LDSM_X4(al[m][0], al[m][1], al[m][2], al[m][3], sA + 10240 + ra);
            }
            // 3 terms, acc target rotates n-fastest -> reuse distance 8
            #pragma unroll
            for (int t = 0; t < 3; t++)
                #pragma unroll
                for (int m = 0; m < 2; m++)
                    #pragma unroll
                    for (int n = 0; n < 8; n++) {
                        const uint32_t* a = (t == 1) ? al[m] : ah[m];
                        uint32_t b0 = (t == 2) ? bl[n][2 * kc]     : bh[n][2 * kc];
                        uint32_t b1 = (t == 2) ? bl[n][2 * kc + 1] : bh[n][2 * kc + 1];
                        mma_bf16(acc[m][n], a, b0, b1);
                    }
        }
    }

    #pragma unroll
    for (int m = 0; m < 2; m++) {
        size_t r0 = m0 + mw * 32 + m * 16 + (lane >> 2);
        #pragma unroll
        for (int n = 0; n < 8; n++) {
            size_t col = n0 + nw * 64 + n * 8 + 2 * (lane & 3);
            *(float2*)&C[r0 * 2048 + col]       = make_float2(acc[m][n][0], acc[m][n][1]);
            *(float2*)&C[(r0 + 8) * 2048 + col] = make_float2(acc[m][n][2], acc[m][n][3]);
        }
    }
}

// ---------------- RoPE (interleaved) + split to bf16 hi/lo ----------------
__global__ void rope_conv_kernel() {
    int idx = blockIdx.x * 256 + threadIdx.x;
    int row = idx >> 10;
    int rem = idx & 1023;
    int head = rem >> 5;
    int i = rem & 31;
    int s = row & (S_ - 1);
    const float* basef = (blockIdx.y == 0 ? g_Q : g_K);
    __nv_bfloat16* dh = (blockIdx.y == 0 ? g_Qbf[0] : g_Kbf[0]);
    __nv_bfloat16* dl = (blockIdx.y == 0 ? g_Qbf[1] : g_Kbf[1]);
    size_t off = (((size_t)row * 32 + head) << 6) + 2 * i;
    float x1 = basef[off], x2 = basef[off + 1];
    float c = g_cos[s * 32 + i], sn = g_sin[s * 32 + i];
    float o1 = x1 * c - x2 * sn;
    float o2 = x1 * sn + x2 * c;
    __nv_bfloat16 h1 = __float2bfloat16(o1), h2 = __float2bfloat16(o2);
    dh[off] = h1;
    dh[off + 1] = h2;
    dl[off] = __float2bfloat16(o1 - __bfloat162float(h1));
    dl[off + 1] = __float2bfloat16(o2 - __bfloat162float(h2));
}

__global__ void vsplit_kernel() {
    size_t i = (size_t)blockIdx.x * 256 + threadIdx.x;
    float v = g_V[i];
    __nv_bfloat16 h = __float2bfloat16(v);
    g_Vbf[0][i] = h;
    g_Vbf[1][i] = __float2bfloat16(v - __bfloat162float(h));
}

// ---------------- flash attention via mma.sync (bf16 3-term split) ----------------
#define FB_BYTES 71680
#define KREG(buf, ss)  ((buf) * FB_BYTES + (ss) * 9216)
#define VREG(buf, hf)  ((buf) * FB_BYTES + 36864 + (hf) * 17408)

__global__ __launch_bounds__(256) void flash_mma_kernel(const float* __restrict__ lnw) {
    extern __shared__ char smem[];
    uint32_t sb = smem_u32(smem);
    __shared__ float sLn[128];

    int tid = threadIdx.x, lane = tid & 31, wid = tid >> 5;
    int stream = wid >> 2, qw = wid & 3;
    int qt = 31 - blockIdx.x;           // heavy tiles first
    int h = blockIdx.y, b = blockIdx.z;
    int q0 = qt * 64;
    int bS = b * S_;
    if (tid < 128) sLn[tid] = lnw[tid];

    // ---- stage Q into buffer 1's K region ----
    for (int i = tid; i < 2048; i += 256) {
        int ss = i >> 9, r = (i >> 3) & 63, c = i & 7;
        uint32_t dst = sb + KREG(1, ss) + r * 144 + c * 16;
        const __nv_bfloat16* src =
            &g_Qbf[ss & 1][(((size_t)(bS + q0 + r) * 32 + 2 * h + (ss >> 1)) << 6) + c * 8];
        CP_ASYNC16(dst, src);
    }
    CP_ASYNC_COMMIT();
    CP_ASYNC_WAIT(0);
    __syncthreads();

    uint32_t qh[4][4], ql[4][4];
    {
        int row = qw * 16 + (lane & 7) + ((lane >> 3) & 1) * 8;
        uint32_t boff = ((lane >> 4) & 1) * 16;
        uint32_t bh_ = sb + KREG(1, stream * 2 + 0) + row * 144 + boff;
        uint32_t bl_ = sb + KREG(1, stream * 2 + 1) + row * 144 + boff;
        #pragma unroll
        for (int kc = 0; kc < 4; kc++) {
            LDSM_X4(qh[kc][0], qh[kc][1], qh[kc][2], qh[kc][3], bh_ + kc * 32);
            LDSM_X4(ql[kc][0], ql[kc][1], ql[kc][2], ql[kc][3], bl_ + kc * 32);
        }
    }
    __syncthreads();

    auto load_tile = [&](int kt) {
        int n0 = kt * 64, buf = kt & 1;
        for (int i = tid; i < 4096; i += 256) {
            uint32_t dst;
            const __nv_bfloat16* src;
            if (i < 2048) {
                int ss = i >> 9, r = (i >> 3) & 63, c = i & 7;
                dst = sb + KREG(buf, ss) + r * 144 + c * 16;
                src = &g_Kbf[ss & 1][(((size_t)(bS + n0 + r) * 32 + 2 * h + (ss >> 1)) << 6) + c * 8];
            } else {
                int j = i - 2048;
                int hf = j >> 10, r = (j >> 4) & 63, c = j & 15;
                dst = sb + VREG(buf, hf) + r * 272 + c * 16;
                src = &g_Vbf[hf][(((size_t)(bS + n0 + r) * 16 + h) << 7) + c * 8];
            }
            CP_ASYNC16(dst, src);
        }
        CP_ASYNC_COMMIT();
    };

    float out[16][4];
    #pragma unroll
    for (int i = 0; i < 16; i++)
        #pragma unroll
        for (int e = 0; e < 4; e++) out[i][e] = 0.f;
    float m0 = -1e30f, m1 = -1e30f, l0 = 0.f, l1 = 0.f;

    load_tile(0);

    int krow = lane & 7;
    uint32_t kboff = (lane >> 3) * 16;
    int vrow = (lane & 7) + ((lane >> 3) & 1) * 8;
    uint32_t vboff = ((lane >> 4) & 1) * 16;

    for (int kt = 0; kt <= qt; kt++) {
        int buf = kt & 1;
        __syncthreads();
        if (kt < qt) { load_tile(kt + 1); CP_ASYNC_WAIT(1); }
        else         { CP_ASYNC_WAIT(0); }
        __syncthreads();

        // ---- scores S = Q K^T, 4 rotating acc targets ----
        float sacc[8][4];
        #pragma unroll
        for (int nt = 0; nt < 8; nt++)
            #pragma unroll
            for (int e = 0; e < 4; e++) sacc[nt][e] = 0.f;

        uint32_t kbh = sb + KREG(buf, stream * 2 + 0);
        uint32_t kbl = sb + KREG(buf, stream * 2 + 1);

        #pragma unroll
        for (int np = 0; np < 4; np++) {
            int ntA = 2 * np, ntB = ntA + 1;
            uint32_t bhA[8], blA[8], bhB[8], blB[8];
            uint32_t raA = (uint32_t)(ntA * 8 + krow) * 144 + kboff;
            uint32_t raB = (uint32_t)(ntB * 8 + krow) * 144 + kboff;
            LDSM_X4(bhA[0], bhA[1], bhA[2], bhA[3], kbh + raA);
            LDSM_X4(bhA[4], bhA[5], bhA[6], bhA[7], kbh + raA + 64);
            LDSM_X4(bhB[0], bhB[1], bhB[2], bhB[3], kbh + raB);
            LDSM_X4(bhB[4], bhB[5], bhB[6], bhB[7], kbh + raB + 64);
            LDSM_X4(blA[0], blA[1], blA[2], blA[3], kbl + raA);
            LDSM_X4(blA[4], blA[5], blA[6], blA[7], kbl + raA + 64);
            LDSM_X4(blB[0], blB[1], blB[2], blB[3], kbl + raB);
            LDSM_X4(blB[4], blB[5], blB[6], blB[7], kbl + raB + 64);
            float tA[4] = {0.f, 0.f, 0.f, 0.f}, tB[4] = {0.f, 0.f, 0.f, 0.f};
            #pragma unroll
            for (int t = 0; t < 3; t++) {
                #pragma unroll
                for (int kc = 0; kc < 4; kc++) {
                    const uint32_t* a = (t == 1) ? ql[kc] : qh[kc];
                    float* dA = (kc & 1) ? tA : sacc[ntA];
                    float* dB = (kc & 1) ? tB : sacc[ntB];
                    uint32_t bA0 = (t == 2) ? blA[2 * kc] : bhA[2 * kc];
                    uint32_t bA1 = (t == 2) ? blA[2 * kc + 1] : bhA[2 * kc + 1];
                    uint32_t bB0 = (t == 2) ? blB[2 * kc] : bhB[2 * kc];
                    uint32_t bB1 = (t == 2) ? blB[2 * kc + 1] : bhB[2 * kc + 1];
                    mma_bf16(dA, a, bA0, bA1);
                    mma_bf16(dB, a, bB0, bB1);
                }
            }
            #pragma unroll
            for (int e = 0; e < 4; e++) { sacc[ntA][e] += tA[e]; sacc[ntB][e] += tB[e]; }
        }

        // ---- online softmax (2 rows per thread) ----
        bool diag = (kt == qt);
        int rlo0 = qw * 16 + (lane >> 2);
        float rm0 = -1e30f, rm1 = -1e30f;
        #pragma unroll
        for (int nt = 0; nt < 8; nt++) {
            #pragma unroll
            for (int e = 0; e < 4; e++) {
                float s = sacc[nt][e] * 0.125f;
                if (diag) {
                    int colL = nt * 8 + 2 * (lane & 3) + (e & 1);
                    int rowL = rlo0 + ((e >> 1) << 3);
                    if (colL > rowL) s = -1e30f;
                }
                sacc[nt][e] = s;
                if (e < 2) rm0 = fmaxf(rm0, s); else rm1 = fmaxf(rm1, s);
            }
        }
        #pragma unroll
        for (int w = 1; w < 4; w <<= 1) {
            rm0 = fmaxf(rm0, __shfl_xor_sync(0xffffffffu, rm0, w));
            rm1 = fmaxf(rm1, __shfl_xor_sync(0xffffffffu, rm1, w));
        }
        float nm0 = fmaxf(m0, rm0), nm1 = fmaxf(m1, rm1);
        float c0 = __expf(m0 - nm0), c1 = __expf(m1 - nm1);
        float ps0 = 0.f, ps1 = 0.f;
        #pragma unroll
        for (int nt = 0; nt < 8; nt++) {
            float p0 = __expf(sacc[nt][0] - nm0);
            float p1 = __expf(sacc[nt][1] - nm0);
            float p2 = __expf(sacc[nt][2] - nm1);
            float p3 = __expf(sacc[nt][3] - nm1);
            sacc[nt][0] = p0; sacc[nt][1] = p1; sacc[nt][2] = p2; sacc[nt][3] = p3;
            ps0 += p0 + p1; ps1 += p2 + p3;
        }
        #pragma unroll
        for (int w = 1; w < 4; w <<= 1) {
            ps0 += __shfl_xor_sync(0xffffffffu, ps0, w);
            ps1 += __shfl_xor_sync(0xffffffffu, ps1, w);
        }
        l0 = l0 * c0 + ps0;
        l1 = l1 * c1 + ps1;
        m0 = nm0; m1 = nm1;
        #pragma unroll
        for (int nt = 0; nt < 16; nt++) {
            out[nt][0] *= c0; out[nt][1] *= c0;
            out[nt][2] *= c1; out[nt][3] *= c1;
        }

        // ---- PV, 4 rotating acc targets per dp-pair ----
        uint32_t vbh = sb + VREG(buf, 0);
        uint32_t vbl = sb + VREG(buf, 1);
        #pragma unroll
        for (int kc2 = 0; kc2 < 4; kc2++) {
            uint32_t pah[4], pal[4];
            split2(sacc[2 * kc2][0], sacc[2 * kc2][1], pah[0], pal[0]);
            split2(sacc[2 * kc2][2], sacc[2 * kc2][3], pah[1], pal[1]);
            split2(sacc[2 * kc2 + 1][0], sacc[2 * kc2 + 1][1], pah[2], pal[2]);
            split2(sacc[2 * kc2 + 1][2], sacc[2 * kc2 + 1][3], pah[3], pal[3]);
            uint32_t vra = (uint32_t)(kc2 * 16 + vrow) * 272 + vboff;
            #pragma unroll
            for (int dpp = 0; dpp < 4; dpp++) {
                int dp0 = 2 * dpp, dp1 = dp0 + 1;
                uint32_t vh0[4], vl0[4], vh1[4], vl1[4];
                LDSM_X4_T(vh0[0], vh0[1], vh0[2], vh0[3], vbh + vra + dp0 * 32);
                LDSM_X4_T(vh1[0], vh1[1], vh1[2], vh1[3], vbh + vra + dp1 * 32);
                LDSM_X4_T(vl0[0], vl0[1], vl0[2], vl0[3], vbl + vra + dp0 * 32);
                LDSM_X4_T(vl1[0], vl1[1], vl1[2], vl1[3], vbl + vra + dp1 * 32);
                #pragma unroll
                for (int t = 0; t < 3; t++) {
                    const uint32_t* p = (t == 1) ? pal : pah;
                    const uint32_t* A0 = (t == 2) ? vl0 : vh0;
                    const uint32_t* A1 = (t == 2) ? vl1 : vh1;
                    mma_bf16(out[2 * dp0],     p, A0[0], A0[1]);
                    mma_bf16(out[2 * dp0 + 1], p, A0[2], A0[3]);
                    mma_bf16(out[2 * dp1],     p, A1[0], A1[1]);
                    mma_bf16(out[2 * dp1 + 1], p, A1[2], A1[3]);
                }
            }
        }
    }

    // ---- epilogue: diff across streams, RMS norm, split-write g_Ahi/g_Alo ----
    float inv0 = 1.f / l0, inv1 = 1.f / l1;
    int r0 = qw * 16 + (lane >> 2);
    float* sX = (float*)smem;
    __syncthreads();
    if (stream == 1) {
        #pragma unroll
        for (int nt = 0; nt < 16; nt++) {
            int col = nt * 8 + 2 * (lane & 3);
            sX[r0 * 132 + col]           = out[nt][0] * inv0;
            sX[r0 * 132 + col + 1]       = out[nt][1] * inv0;
            sX[(r0 + 8) * 132 + col]     = out[nt][2] * inv1;
            sX[(r0 + 8) * 132 + col + 1] = out[nt][3] * inv1;
        }
    }
    __syncthreads();
    if (stream == 0) {
        float lam = g_lambda;
        float ss0 = 0.f, ss1 = 0.f;
        #pragma unroll
        for (int nt = 0; nt < 16; nt++) {
            int col = nt * 8 + 2 * (lane & 3);
            out[nt][0] = out[nt][0] * inv0 - lam * sX[r0 * 132 + col];
            out[nt][1] = out[nt][1] * inv0 - lam * sX[r0 * 132 + col + 1];
            out[nt][2] = out[nt][2] * inv1 - lam * sX[(r0 + 8) * 132 + col];
            out[nt][3] = out[nt][3] * inv1 - lam * sX[(r0 + 8) * 132 + col + 1];
            ss0 += out[nt][0] * out[nt][0] + out[nt][1] * out[nt][1];
            ss1 += out[nt][2] * out[nt][2] + out[nt][3] * out[nt][3];
        }
        #pragma unroll
        for (int w = 1; w < 4; w <<= 1) {
            ss0 += __shfl_xor_sync(0xffffffffu, ss0, w);
            ss1 += __shfl_xor_sync(0xffffffffu, ss1, w);
        }
        float rms0 = rsqrtf(ss0 * (1.f / 128.f) + 1e-5f);
        float rms1 = rsqrtf(ss1 * (1.f / 128.f) + 1e-5f);
        #pragma unroll
        for (int nt = 0; nt < 16; nt++) {
            int col = nt * 8 + 2 * (lane & 3);
            size_t ga = ((size_t)(bS + q0 + r0)) * 2048 + h * 128 + col;
            size_t gb = ((size_t)(bS + q0 + r0 + 8)) * 2048 + h * 128 + col;
            float v0 = out[nt][0] * rms0 * sLn[col] * OUT_SCALE_F;
            float v1 = out[nt][1] * rms0 * sLn[col + 1] * OUT_SCALE_F;
            float v2 = out[nt][2] * rms1 * sLn[col] * OUT_SCALE_F;
            float v3 = out[nt][3] * rms1 * sLn[col + 1] * OUT_SCALE_F;
            __nv_bfloat16 h0 = __float2bfloat16(v0), h1 = __float2bfloat16(v1);
            __nv_bfloat16 h2 = __float2bfloat16(v2), h3 = __float2bfloat16(v3);
            g_Ahi[ga] = h0;     g_Ahi[ga + 1] = h1;
            g_Ahi[gb] = h2;     g_Ahi[gb + 1] = h3;
            g_Alo[ga] = __float2bfloat16(v0 - __bfloat162float(h0));
            g_Alo[ga + 1] = __float2bfloat16(v1 - __bfloat162float(h1));
            g_Alo[gb] = __float2bfloat16(v2 - __bfloat162float(h2));
            g_Alo[gb + 1] = __float2bfloat16(v3 - __bfloat162float(h3));
        }
    }
}

// ---------------- launch ----------------
extern "C" void kernel_launch(void* const* d_in, const int* in_sizes, int n_in,
                              void* d_out, int out_size) {
    const float* x   = (const float*)d_in[0];
    const float* Wq  = (const float*)d_in[1];
    const float* Wk  = (const float*)d_in[2];
    const float* Wv  = (const float*)d_in[3];
    const float* Wo  = (const float*)d_in[4];
    const float* lq1 = (const float*)d_in[5];
    const float* lk1 = (const float*)d_in[6];
    const float* lq2 = (const float*)d_in[7];
    const float* lk2 = (const float*)d_in[8];
    const float* lnw = (const float*)d_in[9];
    float* out = (float*)d_out;

    float *Q, *K, *V;
    __nv_bfloat16 *xhi, *xlo, *Ahi, *Alo, *Wth, *Wtl;
    cudaGetSymbolAddress((void**)&Q, g_Q);
    cudaGetSymbolAddress((void**)&K, g_K);
    cudaGetSymbolAddress((void**)&V, g_V);
    cudaGetSymbolAddress((void**)&xhi, g_xhi);
    cudaGetSymbolAddress((void**)&xlo, g_xlo);
    cudaGetSymbolAddress((void**)&Ahi, g_Ahi);
    cudaGetSymbolAddress((void**)&Alo, g_Alo);
    cudaGetSymbolAddress((void**)&Wth, g_Wt_hi);
    cudaGetSymbolAddress((void**)&Wtl, g_Wt_lo);

    cudaFuncSetAttribute(flash_mma_kernel, cudaFuncAttributeMaxDynamicSharedMemorySize,
                         2 * FB_BYTES);
    cudaFuncSetAttribute(mma_gemm_kernel, cudaFuncAttributeMaxDynamicSharedMemorySize,
                         2 * GS_BYTES);

    prep_tables_kernel<<<S_, 32>>>();
    prep_lambda_kernel<<<1, 64>>>(lq1, lk1, lq2, lk2);

    split_x_kernel<<<((size_t)ROWS_ * E_) / 256, 256>>>(x);
    dim3 tg(E_ / 32, E_ / 32), tb(32, 8);
    transpose_split_kernel<<<tg, tb>>>(Wq, Wth + 0L * E_ * E_, Wtl + 0L * E_ * E_);
    transpose_split_kernel<<<tg, tb>>>(Wk, Wth + 1L * E_ * E_, Wtl + 1L * E_ * E_);
    transpose_split_kernel<<<tg, tb>>>(Wv, Wth + 2L * E_ * E_, Wtl + 2L * E_ * E_);
    transpose_split_kernel<<<tg, tb>>>(Wo, Wth + 3L * E_ * E_, Wtl + 3L * E_ * E_);

    dim3 gg(E_ / 128, ROWS_ / 128);
    size_t gsmem = 2 * GS_BYTES;
    mma_gemm_kernel<<<gg, 256, gsmem>>>(xhi, xlo, Wth + 0L * E_ * E_, Wtl + 0L * E_ * E_, Q);
    mma_gemm_kernel<<<gg, 256, gsmem>>>(xhi, xlo, Wth + 1L * E_ * E_, Wtl + 1L * E_ * E_, K);
    mma_gemm_kernel<<<gg, 256, gsmem>>>(xhi, xlo, Wth + 2L * E_ * E_, Wtl + 2L * E_ * E_, V);

    dim3 rg((ROWS_ * 1024) / 256, 2);
    rope_conv_kernel<<<rg, 256>>>();
    vsplit_kernel<<<((size_t)ROWS_ * E_) / 256, 256>>>();

    dim3 fg(32, 16, 2);
    flash_mma_kernel<<<fg, 256, 2 * FB_BYTES>>>(lnw);

    mma_gemm_kernel<<<gg, 256, gsmem>>>(Ahi, Alo, Wth + 3L * E_ * E_, Wtl + 3L * E_ * E_, out);
}

// round 6
// speedup vs baseline: 4.6410x; 1.0561x over previous
#include <cuda_runtime.h>
#include <cuda_bf16.h>
#include <cstdint>

#define B_ 2
#define S_ 2048
#define E_ 2048
#define H_ 16
#define HD_ 64
#define ROWS_ (B_ * S_)          // 4096
#define LAMBDA_INIT_F 0.783605766532f
#define OUT_SCALE_F   0.216394233468f   // 1 - LAMBDA_INIT

// ---------------- scratch (device globals; no allocations) ----------------
__device__ float g_Q[(size_t)ROWS_ * E_];     // [B,S,2H,HD] fp32 (pre-rope)
__device__ float g_K[(size_t)ROWS_ * E_];
__device__ float g_V[(size_t)ROWS_ * E_];     // [B,S,H,2HD] fp32
__device__ __nv_bfloat16 g_xhi[(size_t)ROWS_ * E_];
__device__ __nv_bfloat16 g_xlo[(size_t)ROWS_ * E_];
__device__ __nv_bfloat16 g_Ahi[(size_t)ROWS_ * E_];   // flash output split
__device__ __nv_bfloat16 g_Alo[(size_t)ROWS_ * E_];
__device__ __nv_bfloat16 g_Wt_hi[4][(size_t)E_ * E_]; // transposed weights [n][k]: q,k,v,o
__device__ __nv_bfloat16 g_Wt_lo[4][(size_t)E_ * E_];
__device__ __nv_bfloat16 g_Qbf[2][(size_t)ROWS_ * E_];  // [half][(row*32+head)*64+d] post-rope
__device__ __nv_bfloat16 g_Kbf[2][(size_t)ROWS_ * E_];
__device__ __nv_bfloat16 g_Vbf[2][(size_t)ROWS_ * E_];  // [half][(row*16+h)*128+d]
__device__ float g_cos[S_ * 32];
__device__ float g_sin[S_ * 32];
__device__ float g_lambda;

// ---------------- small helpers ----------------
__device__ __forceinline__ uint32_t smem_u32(const void* p) {
    uint32_t a;
    asm("{ .reg .u64 t; cvta.to.shared.u64 t, %1; cvt.u32.u64 %0, t; }" : "=r"(a) : "l"(p));
    return a;
}
#define CP_ASYNC16(dst, src) \
    asm volatile("cp.async.cg.shared.global [%0], [%1], 16;" :: "r"(dst), "l"(src))
#define CP_ASYNC_COMMIT() asm volatile("cp.async.commit_group;" ::: "memory")
#define CP_ASYNC_WAIT(n)  asm volatile("cp.async.wait_group %0;" :: "n"(n) : "memory")

#define LDSM_X4(r0, r1, r2, r3, addr) \
    asm volatile("ldmatrix.sync.aligned.m8n8.x4.shared.b16 {%0,%1,%2,%3}, [%4];" \
                 : "=r"(r0), "=r"(r1), "=r"(r2), "=r"(r3) : "r"(addr))
#define LDSM_X4_T(r0, r1, r2, r3, addr) \
    asm volatile("ldmatrix.sync.aligned.m8n8.x4.trans.shared.b16 {%0,%1,%2,%3}, [%4];" \
                 : "=r"(r0), "=r"(r1), "=r"(r2), "=r"(r3) : "r"(addr))

__device__ __forceinline__ void mma_bf16(float* c, const uint32_t* a, uint32_t b0, uint32_t b1) {
    asm volatile(
        "mma.sync.aligned.m16n8k16.row.col.f32.bf16.bf16.f32 "
        "{%0,%1,%2,%3}, {%4,%5,%6,%7}, {%8,%9}, {%0,%1,%2,%3};"
        : "+f"(c[0]), "+f"(c[1]), "+f"(c[2]), "+f"(c[3])
        : "r"(a[0]), "r"(a[1]), "r"(a[2]), "r"(a[3]), "r"(b0), "r"(b1));
}

// split two floats into packed bf16 hi pair + lo pair
__device__ __forceinline__ void split2(float x, float y, uint32_t& hi, uint32_t& lo) {
    __nv_bfloat162 h2 = __floats2bfloat162_rn(x, y);
    float2 hf = __bfloat1622float2(h2);
    __nv_bfloat162 l2 = __floats2bfloat162_rn(x - hf.x, y - hf.y);
    hi = *(uint32_t*)&h2;
    lo = *(uint32_t*)&l2;
}

// ---------------- prep: rope tables + lambda (merged) ----------------
__global__ void prep_kernel(const float* __restrict__ lq1, const float* __restrict__ lk1,
                            const float* __restrict__ lq2, const float* __restrict__ lk2) {
    if (blockIdx.x < 1024) {
        int t = blockIdx.x * 2 + (threadIdx.x >> 5);
        int i = threadIdx.x & 31;
        float inv = (float)pow(10000.0, -(double)i / 32.0);
        float f = (float)t * inv;
        g_cos[t * 32 + i] = cosf(f);
        g_sin[t * 32 + i] = sinf(f);
    } else {
        __shared__ float s1[64], s2[64];
        int i = threadIdx.x;
        s1[i] = lq1[i] * lk1[i];
        s2[i] = lq2[i] * lk2[i];
        __syncthreads();
        if (i == 0) {
            float a = 0.f, b = 0.f;
            for (int j = 0; j < 64; j++) { a += s1[j]; b += s2[j]; }
            g_lambda = expf(a) - expf(b) + LAMBDA_INIT_F;
        }
    }
}

// ---------------- split x into bf16 hi/lo ----------------
__global__ void split_x_kernel(const float* __restrict__ x) {
    size_t i = (size_t)blockIdx.x * 256 + threadIdx.x;
    float v = x[i];
    __nv_bfloat16 h = __float2bfloat16(v);
    g_xhi[i] = h;
    g_xlo[i] = __float2bfloat16(v - __bfloat162float(h));
}

// ---------------- transpose + split all 4 weights (fused) ----------------
__global__ void transpose_split_kernel(const float* __restrict__ Wq, const float* __restrict__ Wk,
                                       const float* __restrict__ Wv, const float* __restrict__ Wo) {
    __shared__ float t[32][33];
    int w = blockIdx.z;
    const float* W = (w == 0) ? Wq : (w == 1) ? Wk : (w == 2) ? Wv : Wo;
    __nv_bfloat16* hi = g_Wt_hi[w];
    __nv_bfloat16* lo = g_Wt_lo[w];
    int k0 = blockIdx.x * 32, n0 = blockIdx.y * 32;
    int tx = threadIdx.x, ty = threadIdx.y;   // 32 x 8
    #pragma unroll
    for (int j = 0; j < 32; j += 8)
        t[ty + j][tx] = W[(size_t)(k0 + ty + j) * E_ + n0 + tx];
    __syncthreads();
    #pragma unroll
    for (int j = 0; j < 32; j += 8) {
        float v = t[tx][ty + j];
        size_t o = (size_t)(n0 + ty + j) * E_ + k0 + tx;
        __nv_bfloat16 h = __float2bfloat16(v);
        hi[o] = h;
        lo[o] = __float2bfloat16(v - __bfloat162float(h));
    }
}

// ---------------- mma.sync bf16 3-term GEMM: C = A @ B^T (fused multi-output) ----------------
// Tile BM=128 BN=128 BK=32, 8 warps (4m x 2n), warp tile m32 n64.
// 3-stage cp.async pipeline, ONE __syncthreads per K-iter.
// grid.x = 16 * num_mats; sel = sel_base + bx/16 picks weight matrix & output.
#define GS_BYTES 40960   // per stage: Ahi 10240 | Alo 10240 | Bhi 10240 | Blo 10240

__global__ __launch_bounds__(256, 1) void mma_gemm_kernel(
    const __nv_bfloat16* __restrict__ Ahi, const __nv_bfloat16* __restrict__ Alo,
    const __nv_bfloat16* __restrict__ BhiBase, const __nv_bfloat16* __restrict__ BloBase,
    float* __restrict__ C0, float* __restrict__ C1, float* __restrict__ C2,
    int sel_base)
{
    extern __shared__ char smem[];
    uint32_t sb = smem_u32(smem);
    int tid = threadIdx.x, lane = tid & 31, wid = tid >> 5;
    int mw = wid >> 1, nw = wid & 1;
    int msel = blockIdx.x >> 4;
    int sel = sel_base + msel;
    const __nv_bfloat16* Bhi = BhiBase + (size_t)sel * E_ * E_;
    const __nv_bfloat16* Blo = BloBase + (size_t)sel * E_ * E_;
    float* C = (msel == 0) ? C0 : (msel == 1) ? C1 : C2;
    int m0 = blockIdx.y * 128, n0 = (blockIdx.x & 15) * 128;

    auto load_stage = [&](int it) {
        int s = it % 3;
        int k0 = it * 32;
        uint32_t st = sb + s * GS_BYTES;
        #pragma unroll
        for (int c = tid; c < 2048; c += 256) {
            int mat = c >> 10;            // 0=A, 1=B
            int cc = c & 1023;
            int p = cc >> 9;              // 0=hi, 1=lo
            int r = (cc >> 2) & 127;
            int ch = cc & 3;
            const __nv_bfloat16* src =
                (mat ? (p ? Blo : Bhi) + (size_t)(n0 + r) * 2048
                     : (p ? Alo : Ahi) + (size_t)(m0 + r) * 2048) + k0 + ch * 8;
            uint32_t dst = st + mat * 20480 + p * 10240 + r * 80 + ch * 16;
            CP_ASYNC16(dst, src);
        }
        CP_ASYNC_COMMIT();
    };

    float acc[2][8][4];
    #pragma unroll
    for (int m = 0; m < 2; m++)
        #pragma unroll
        for (int n = 0; n < 8; n++)
            #pragma unroll
            for (int e = 0; e < 4; e++) acc[m][n][e] = 0.f;

    load_stage(0);
    load_stage(1);

    int krow = lane & 7;
    uint32_t kboff = (lane >> 3) * 16;
    int arow = (lane & 7) + ((lane >> 3) & 1) * 8;
    uint32_t aboff = ((lane >> 4) & 1) * 16;

    for (int it = 0; it < 64; it++) {
        int s = it % 3;
        if (it < 63) CP_ASYNC_WAIT(1);
        else         CP_ASYNC_WAIT(0);
        __syncthreads();
        if (it + 2 < 64) load_stage(it + 2);

        uint32_t sA = sb + s * GS_BYTES;
        uint32_t sB = sA + 20480;

        uint32_t bh[8][4], bl[8][4];
        #pragma unroll
        for (int n = 0; n < 8; n++) {
            uint32_t ra = (uint32_t)(nw * 64 + n * 8 + krow) * 80 + kboff;
            LDSM_X4(bh[n][0], bh[n][1], bh[n][2], bh[n][3], sB + ra);
            LDSM_X4(bl[n][0], bl[n][1], bl[n][2], bl[n][3], sB + 10240 + ra);
        }

        #pragma unroll
        for (int kc = 0; kc < 2; kc++) {
            uint32_t ah[2][4], al[2][4];
            #pragma unroll
            for (int m = 0; m < 2; m++) {
                uint32_t ra = (uint32_t)(mw * 32 + m * 16 + arow) * 80 + aboff + kc * 32;
                LDSM_X4(ah[m][0], ah[m][1], ah[m][2], ah[m][3], sA + ra);
                LDSM_X4(al[m][0], al[m][1], al[m][2], al[m][3], sA + 10240 + ra);
            }
            #pragma unroll
            for (int t = 0; t < 3; t++)
                #pragma unroll
                for (int m = 0; m < 2; m++)
                    #pragma unroll
                    for (int n = 0; n < 8; n++) {
                        const uint32_t* a = (t == 1) ? al[m] : ah[m];
                        uint32_t b0 = (t == 2) ? bl[n][2 * kc]     : bh[n][2 * kc];
                        uint32_t b1 = (t == 2) ? bl[n][2 * kc + 1] : bh[n][2 * kc + 1];
                        mma_bf16(acc[m][n], a, b0, b1);
                    }
        }
    }

    #pragma unroll
    for (int m = 0; m < 2; m++) {
        size_t r0 = m0 + mw * 32 + m * 16 + (lane >> 2);
        #pragma unroll
        for (int n = 0; n < 8; n++) {
            size_t col = n0 + nw * 64 + n * 8 + 2 * (lane & 3);
            *(float2*)&C[r0 * 2048 + col]       = make_float2(acc[m][n][0], acc[m][n][1]);
            *(float2*)&C[(r0 + 8) * 2048 + col] = make_float2(acc[m][n][2], acc[m][n][3]);
        }
    }
}

// ---------------- RoPE Q/K + V split (merged) ----------------
// grid: (32768, 3): y=0 Q-rope, y=1 K-rope (first 16384 blocks), y=2 V-split
__global__ void rope_v_kernel() {
    if (blockIdx.y < 2) {
        int idx = blockIdx.x * 256 + threadIdx.x;
        if (blockIdx.x >= 16384) return;
        int row = idx >> 10;
        int rem = idx & 1023;
        int head = rem >> 5;
        int i = rem & 31;
        int s = row & (S_ - 1);
        const float* basef = (blockIdx.y == 0 ? g_Q : g_K);
        __nv_bfloat16* dh = (blockIdx.y == 0 ? g_Qbf[0] : g_Kbf[0]);
        __nv_bfloat16* dl = (blockIdx.y == 0 ? g_Qbf[1] : g_Kbf[1]);
        size_t off = (((size_t)row * 32 + head) << 6) + 2 * i;
        float x1 = basef[off], x2 = basef[off + 1];
        float c = g_cos[s * 32 + i], sn = g_sin[s * 32 + i];
        float o1 = x1 * c - x2 * sn;
        float o2 = x1 * sn + x2 * c;
        __nv_bfloat16 h1 = __float2bfloat16(o1), h2 = __float2bfloat16(o2);
        dh[off] = h1;
        dh[off + 1] = h2;
        dl[off] = __float2bfloat16(o1 - __bfloat162float(h1));
        dl[off + 1] = __float2bfloat16(o2 - __bfloat162float(h2));
    } else {
        size_t i = (size_t)blockIdx.x * 256 + threadIdx.x;
        float v = g_V[i];
        __nv_bfloat16 h = __float2bfloat16(v);
        g_Vbf[0][i] = h;
        g_Vbf[1][i] = __float2bfloat16(v - __bfloat162float(h));
    }
}

// ---------------- flash attention via mma.sync (bf16 3-term split) ----------------
// 3-stage pipeline, ONE __syncthreads per key-tile.
#define FB_BYTES 71680
#define KREG(buf, ss)  ((buf) * FB_BYTES + (ss) * 9216)
#define VREG(buf, hf)  ((buf) * FB_BYTES + 36864 + (hf) * 17408)

__global__ __launch_bounds__(256) void flash_mma_kernel(const float* __restrict__ lnw) {
    extern __shared__ char smem[];
    uint32_t sb = smem_u32(smem);
    __shared__ float sLn[128];

    int tid = threadIdx.x, lane = tid & 31, wid = tid >> 5;
    int stream = wid >> 2, qw = wid & 3;
    int qt = 31 - blockIdx.x;           // heavy tiles first
    int h = blockIdx.y, b = blockIdx.z;
    int q0 = qt * 64;
    int bS = b * S_;
    if (tid < 128) sLn[tid] = lnw[tid];

    auto load_tile = [&](int kt) {
        int n0 = kt * 64, buf = kt % 3;
        for (int i = tid; i < 4096; i += 256) {
            uint32_t dst;
            const __nv_bfloat16* src;
            if (i < 2048) {
                int ss = i >> 9, r = (i >> 3) & 63, c = i & 7;
                dst = sb + KREG(buf, ss) + r * 144 + c * 16;
                src = &g_Kbf[ss & 1][(((size_t)(bS + n0 + r) * 32 + 2 * h + (ss >> 1)) << 6) + c * 8];
            } else {
                int j = i - 2048;
                int hf = j >> 10, r = (j >> 4) & 63, c = j & 15;
                dst = sb + VREG(buf, hf) + r * 272 + c * 16;
                src = &g_Vbf[hf][(((size_t)(bS + n0 + r) * 16 + h) << 7) + c * 8];
            }
            CP_ASYNC16(dst, src);
        }
        CP_ASYNC_COMMIT();
    };

    // ---- stage Q into buffer 2's K region, plus prefetch tiles 0,1 ----
    for (int i = tid; i < 2048; i += 256) {
        int ss = i >> 9, r = (i >> 3) & 63, c = i & 7;
        uint32_t dst = sb + KREG(2, ss) + r * 144 + c * 16;
        const __nv_bfloat16* src =
            &g_Qbf[ss & 1][(((size_t)(bS + q0 + r) * 32 + 2 * h + (ss >> 1)) << 6) + c * 8];
        CP_ASYNC16(dst, src);
    }
    CP_ASYNC_COMMIT();
    load_tile(0);
    if (qt >= 1) { load_tile(1); CP_ASYNC_WAIT(1); }
    else         { CP_ASYNC_WAIT(0); }
    __syncthreads();

    uint32_t qh[4][4], ql[4][4];
    {
        int row = qw * 16 + (lane & 7) + ((lane >> 3) & 1) * 8;
        uint32_t boff = ((lane >> 4) & 1) * 16;
        uint32_t bh_ = sb + KREG(2, stream * 2 + 0) + row * 144 + boff;
        uint32_t bl_ = sb + KREG(2, stream * 2 + 1) + row * 144 + boff;
        #pragma unroll
        for (int kc = 0; kc < 4; kc++) {
            LDSM_X4(qh[kc][0], qh[kc][1], qh[kc][2], qh[kc][3], bh_ + kc * 32);
            LDSM_X4(ql[kc][0], ql[kc][1], ql[kc][2], ql[kc][3], bl_ + kc * 32);
        }
    }

    float out[16][4];
    #pragma unroll
    for (int i = 0; i < 16; i++)
        #pragma unroll
        for (int e = 0; e < 4; e++) out[i][e] = 0.f;
    float m0 = -1e30f, m1 = -1e30f, l0 = 0.f, l1 = 0.f;

    int krow = lane & 7;
    uint32_t kboff = (lane >> 3) * 16;
    int vrow = (lane & 7) + ((lane >> 3) & 1) * 8;
    uint32_t vboff = ((lane >> 4) & 1) * 16;

    for (int kt = 0; kt <= qt; kt++) {
        int buf = kt % 3;
        if (kt < qt) CP_ASYNC_WAIT(1);
        else         CP_ASYNC_WAIT(0);
        __syncthreads();
        if (kt + 2 <= qt) load_tile(kt + 2);

        // ---- scores S = Q K^T, rotating acc targets ----
        float sacc[8][4];
        #pragma unroll
        for (int nt = 0; nt < 8; nt++)
            #pragma unroll
            for (int e = 0; e < 4; e++) sacc[nt][e] = 0.f;

        uint32_t kbh = sb + KREG(buf, stream * 2 + 0);
        uint32_t kbl = sb + KREG(buf, stream * 2 + 1);

        #pragma unroll
        for (int np = 0; np < 4; np++) {
            int ntA = 2 * np, ntB = ntA + 1;
            uint32_t bhA[8], blA[8], bhB[8], blB[8];
            uint32_t raA = (uint32_t)(ntA * 8 + krow) * 144 + kboff;
            uint32_t raB = (uint32_t)(ntB * 8 + krow) * 144 + kboff;
            LDSM_X4(bhA[0], bhA[1], bhA[2], bhA[3], kbh + raA);
            LDSM_X4(bhA[4], bhA[5], bhA[6], bhA[7], kbh + raA + 64);
            LDSM_X4(bhB[0], bhB[1], bhB[2], bhB[3], kbh + raB);
            LDSM_X4(bhB[4], bhB[5], bhB[6], bhB[7], kbh + raB + 64);
            LDSM_X4(blA[0], blA[1], blA[2], blA[3], kbl + raA);
            LDSM_X4(blA[4], blA[5], blA[6], blA[7], kbl + raA + 64);
            LDSM_X4(blB[0], blB[1], blB[2], blB[3], kbl + raB);
            LDSM_X4(blB[4], blB[5], blB[6], blB[7], kbl + raB + 64);
            float tA[4] = {0.f, 0.f, 0.f, 0.f}, tB[4] = {0.f, 0.f, 0.f, 0.f};
            #pragma unroll
            for (int t = 0; t < 3; t++) {
                #pragma unroll
                for (int kc = 0; kc < 4; kc++) {
                    const uint32_t* a = (t == 1) ? ql[kc] : qh[kc];
                    float* dA = (kc & 1) ? tA : sacc[ntA];
                    float* dB = (kc & 1) ? tB : sacc[ntB];
                    uint32_t bA0 = (t == 2) ? blA[2 * kc] : bhA[2 * kc];
                    uint32_t bA1 = (t == 2) ? blA[2 * kc + 1] : bhA[2 * kc + 1];
                    uint32_t bB0 = (t == 2) ? blB[2 * kc] : bhB[2 * kc];
                    uint32_t bB1 = (t == 2) ? blB[2 * kc + 1] : bhB[2 * kc + 1];
                    mma_bf16(dA, a, bA0, bA1);
                    mma_bf16(dB, a, bB0, bB1);
                }
            }
            #pragma unroll
            for (int e = 0; e < 4; e++) { sacc[ntA][e] += tA[e]; sacc[ntB][e] += tB[e]; }
        }

        // ---- online softmax (2 rows per thread) ----
        bool diag = (kt == qt);
        int rlo0 = qw * 16 + (lane >> 2);
        float rm0 = -1e30f, rm1 = -1e30f;
        #pragma unroll
        for (int nt = 0; nt < 8; nt++) {
            #pragma unroll
            for (int e = 0; e < 4; e++) {
                float s = sacc[nt][e] * 0.125f;
                if (diag) {
                    int colL = nt * 8 + 2 * (lane & 3) + (e & 1);
                    int rowL = rlo0 + ((e >> 1) << 3);
                    if (colL > rowL) s = -1e30f;
                }
                sacc[nt][e] = s;
                if (e < 2) rm0 = fmaxf(rm0, s); else rm1 = fmaxf(rm1, s);
            }
        }
        #pragma unroll
        for (int w = 1; w < 4; w <<= 1) {
            rm0 = fmaxf(rm0, __shfl_xor_sync(0xffffffffu, rm0, w));
            rm1 = fmaxf(rm1, __shfl_xor_sync(0xffffffffu, rm1, w));
        }
        float nm0 = fmaxf(m0, rm0), nm1 = fmaxf(m1, rm1);
        float c0 = __expf(m0 - nm0), c1 = __expf(m1 - nm1);
        float ps0 = 0.f, ps1 = 0.f;
        #pragma unroll
        for (int nt = 0; nt < 8; nt++) {
            float p0 = __expf(sacc[nt][0] - nm0);
            float p1 = __expf(sacc[nt][1] - nm0);
            float p2 = __expf(sacc[nt][2] - nm1);
            float p3 = __expf(sacc[nt][3] - nm1);
            sacc[nt][0] = p0; sacc[nt][1] = p1; sacc[nt][2] = p2; sacc[nt][3] = p3;
            ps0 += p0 + p1; ps1 += p2 + p3;
        }
        #pragma unroll
        for (int w = 1; w < 4; w <<= 1) {
            ps0 += __shfl_xor_sync(0xffffffffu, ps0, w);
            ps1 += __shfl_xor_sync(0xffffffffu, ps1, w);
        }
        l0 = l0 * c0 + ps0;
        l1 = l1 * c1 + ps1;
        m0 = nm0; m1 = nm1;
        #pragma unroll
        for (int nt = 0; nt < 16; nt++) {
            out[nt][0] *= c0; out[nt][1] *= c0;
            out[nt][2] *= c1; out[nt][3] *= c1;
        }

        // ---- PV, rotating acc targets ----
        uint32_t vbh = sb + VREG(buf, 0);
        uint32_t vbl = sb + VREG(buf, 1);
        #pragma unroll
        for (int kc2 = 0; kc2 < 4; kc2++) {
            uint32_t pah[4], pal[4];
            split2(sacc[2 * kc2][0], sacc[2 * kc2][1], pah[0], pal[0]);
            split2(sacc[2 * kc2][2], sacc[2 * kc2][3], pah[1], pal[1]);
            split2(sacc[2 * kc2 + 1][0], sacc[2 * kc2 + 1][1], pah[2], pal[2]);
            split2(sacc[2 * kc2 + 1][2], sacc[2 * kc2 + 1][3], pah[3], pal[3]);
            uint32_t vra = (uint32_t)(kc2 * 16 + vrow) * 272 + vboff;
            #pragma unroll
            for (int dpp = 0; dpp < 4; dpp++) {
                int dp0 = 2 * dpp, dp1 = dp0 + 1;
                uint32_t vh0[4], vl0[4], vh1[4], vl1[4];
                LDSM_X4_T(vh0[0], vh0[1], vh0[2], vh0[3], vbh + vra + dp0 * 32);
                LDSM_X4_T(vh1[0], vh1[1], vh1[2], vh1[3], vbh + vra + dp1 * 32);
                LDSM_X4_T(vl0[0], vl0[1], vl0[2], vl0[3], vbl + vra + dp0 * 32);
                LDSM_X4_T(vl1[0], vl1[1], vl1[2], vl1[3], vbl + vra + dp1 * 32);
                #pragma unroll
                for (int t = 0; t < 3; t++) {
                    const uint32_t* p = (t == 1) ? pal : pah;
                    const uint32_t* A0 = (t == 2) ? vl0 : vh0;
                    const uint32_t* A1 = (t == 2) ? vl1 : vh1;
                    mma_bf16(out[2 * dp0],     p, A0[0], A0[1]);
                    mma_bf16(out[2 * dp0 + 1], p, A0[2], A0[3]);
                    mma_bf16(out[2 * dp1],     p, A1[0], A1[1]);
                    mma_bf16(out[2 * dp1 + 1], p, A1[2], A1[3]);
                }
            }
        }
    }

    // ---- epilogue: diff across streams, RMS norm, split-write g_Ahi/g_Alo ----
    float inv0 = 1.f / l0, inv1 = 1.f / l1;
    int r0 = qw * 16 + (lane >> 2);
    float* sX = (float*)smem;
    __syncthreads();
    if (stream == 1) {
        #pragma unroll
        for (int nt = 0; nt < 16; nt++) {
            int col = nt * 8 + 2 * (lane & 3);
            sX[r0 * 132 + col]           = out[nt][0] * inv0;
            sX[r0 * 132 + col + 1]       = out[nt][1] * inv0;
            sX[(r0 + 8) * 132 + col]     = out[nt][2] * inv1;
            sX[(r0 + 8) * 132 + col + 1] = out[nt][3] * inv1;
        }
    }
    __syncthreads();
    if (stream == 0) {
        float lam = g_lambda;
        float ss0 = 0.f, ss1 = 0.f;
        #pragma unroll
        for (int nt = 0; nt < 16; nt++) {
            int col = nt * 8 + 2 * (lane & 3);
            out[nt][0] = out[nt][0] * inv0 - lam * sX[r0 * 132 + col];
            out[nt][1] = out[nt][1] * inv0 - lam * sX[r0 * 132 + col + 1];
            out[nt][2] = out[nt][2] * inv1 - lam * sX[(r0 + 8) * 132 + col];
            out[nt][3] = out[nt][3] * inv1 - lam * sX[(r0 + 8) * 132 + col + 1];
            ss0 += out[nt][0] * out[nt][0] + out[nt][1] * out[nt][1];
            ss1 += out[nt][2] * out[nt][2] + out[nt][3] * out[nt][3];
        }
        #pragma unroll
        for (int w = 1; w < 4; w <<= 1) {
            ss0 += __shfl_xor_sync(0xffffffffu, ss0, w);
            ss1 += __shfl_xor_sync(0xffffffffu, ss1, w);
        }
        float rms0 = rsqrtf(ss0 * (1.f / 128.f) + 1e-5f);
        float rms1 = rsqrtf(ss1 * (1.f / 128.f) + 1e-5f);
        #pragma unroll
        for (int nt = 0; nt < 16; nt++) {
            int col = nt * 8 + 2 * (lane & 3);
            size_t ga = ((size_t)(bS + q0 + r0)) * 2048 + h * 128 + col;
            size_t gb = ((size_t)(bS + q0 + r0 + 8)) * 2048 + h * 128 + col;
            float v0 = out[nt][0] * rms0 * sLn[col] * OUT_SCALE_F;
            float v1 = out[nt][1] * rms0 * sLn[col + 1] * OUT_SCALE_F;
            float v2 = out[nt][2] * rms1 * sLn[col] * OUT_SCALE_F;
            float v3 = out[nt][3] * rms1 * sLn[col + 1] * OUT_SCALE_F;
            __nv_bfloat16 h0 = __float2bfloat16(v0), h1 = __float2bfloat16(v1);
            __nv_bfloat16 h2 = __float2bfloat16(v2), h3 = __float2bfloat16(v3);
            g_Ahi[ga] = h0;     g_Ahi[ga + 1] = h1;
            g_Ahi[gb] = h2;     g_Ahi[gb + 1] = h3;
            g_Alo[ga] = __float2bfloat16(v0 - __bfloat162float(h0));
            g_Alo[ga + 1] = __float2bfloat16(v1 - __bfloat162float(h1));
            g_Alo[gb] = __float2bfloat16(v2 - __bfloat162float(h2));
            g_Alo[gb + 1] = __float2bfloat16(v3 - __bfloat162float(h3));
        }
    }
}

// ---------------- launch ----------------
extern "C" void kernel_launch(void* const* d_in, const int* in_sizes, int n_in,
                              void* d_out, int out_size) {
    const float* x   = (const float*)d_in[0];
    const float* Wq  = (const float*)d_in[1];
    const float* Wk  = (const float*)d_in[2];
    const float* Wv  = (const float*)d_in[3];
    const float* Wo  = (const float*)d_in[4];
    const float* lq1 = (const float*)d_in[5];
    const float* lk1 = (const float*)d_in[6];
    const float* lq2 = (const float*)d_in[7];
    const float* lk2 = (const float*)d_in[8];
    const float* lnw = (const float*)d_in[9];
    float* out = (float*)d_out;

    float *Q, *K, *V;
    __nv_bfloat16 *xhi, *xlo, *Ahi, *Alo, *Wth, *Wtl;
    cudaGetSymbolAddress((void**)&Q, g_Q);
    cudaGetSymbolAddress((void**)&K, g_K);
    cudaGetSymbolAddress((void**)&V, g_V);
    cudaGetSymbolAddress((void**)&xhi, g_xhi);
    cudaGetSymbolAddress((void**)&xlo, g_xlo);
    cudaGetSymbolAddress((void**)&Ahi, g_Ahi);
    cudaGetSymbolAddress((void**)&Alo, g_Alo);
    cudaGetSymbolAddress((void**)&Wth, g_Wt_hi);
    cudaGetSymbolAddress((void**)&Wtl, g_Wt_lo);

    cudaFuncSetAttribute(flash_mma_kernel, cudaFuncAttributeMaxDynamicSharedMemorySize,
                         3 * FB_BYTES);
    cudaFuncSetAttribute(mma_gemm_kernel, cudaFuncAttributeMaxDynamicSharedMemorySize,
                         3 * GS_BYTES);

    // launch order arranged so ncu (-s 5 -c 1) captures flash_mma_kernel (#6)
    prep_kernel<<<1025, 64>>>(lq1, lk1, lq2, lk2);                       // 1
    dim3 tg(E_ / 32, E_ / 32, 4), tb(32, 8);
    transpose_split_kernel<<<tg, tb>>>(Wq, Wk, Wv, Wo);                  // 2
    split_x_kernel<<<((size_t)ROWS_ * E_) / 256, 256>>>(x);              // 3

    size_t gsmem = 3 * GS_BYTES;
    dim3 gqkv(48, ROWS_ / 128);
    mma_gemm_kernel<<<gqkv, 256, gsmem>>>(xhi, xlo, Wth, Wtl, Q, K, V, 0);   // 4

    dim3 rvg(32768, 3);
    rope_v_kernel<<<rvg, 256>>>();                                       // 5

    dim3 fg(32, 16, 2);
    flash_mma_kernel<<<fg, 256, 3 * FB_BYTES>>>(lnw);                    // 6  <- profiled

    dim3 go(16, ROWS_ / 128);
    mma_gemm_kernel<<<go, 256, gsmem>>>(Ahi, Alo, Wth, Wtl, out, out, out, 3); // 7
}

// round 7
// speedup vs baseline: 4.8802x; 1.0516x over previous
#include <cuda_runtime.h>
#include <cuda_bf16.h>
#include <cstdint>

#define B_ 2
#define S_ 2048
#define E_ 2048
#define H_ 16
#define HD_ 64
#define ROWS_ (B_ * S_)          // 4096
#define LAMBDA_INIT_F 0.783605766532f
#define OUT_SCALE_F   0.216394233468f   // 1 - LAMBDA_INIT

// ---------------- scratch (device globals; no allocations) ----------------
__device__ __nv_bfloat16 g_xhi[(size_t)ROWS_ * E_];
__device__ __nv_bfloat16 g_xlo[(size_t)ROWS_ * E_];
__device__ __nv_bfloat16 g_Ahi[(size_t)ROWS_ * E_];   // flash output split
__device__ __nv_bfloat16 g_Alo[(size_t)ROWS_ * E_];
__device__ __nv_bfloat16 g_Wt_hi[4][(size_t)E_ * E_]; // transposed weights [n][k]: q,k,v,o
__device__ __nv_bfloat16 g_Wt_lo[4][(size_t)E_ * E_];
__device__ __nv_bfloat16 g_Qbf[2][(size_t)ROWS_ * E_];  // [half][row*2048 + head*64 + d] post-rope
__device__ __nv_bfloat16 g_Kbf[2][(size_t)ROWS_ * E_];
__device__ __nv_bfloat16 g_Vbf[2][(size_t)ROWS_ * E_];  // [half][row*2048 + h*128 + d]
__device__ float g_cos[S_ * 32];
__device__ float g_sin[S_ * 32];
__device__ float g_lambda;

// ---------------- small helpers ----------------
__device__ __forceinline__ uint32_t smem_u32(const void* p) {
    uint32_t a;
    asm("{ .reg .u64 t; cvta.to.shared.u64 t, %1; cvt.u32.u64 %0, t; }" : "=r"(a) : "l"(p));
    return a;
}
#define CP_ASYNC16(dst, src) \
    asm volatile("cp.async.cg.shared.global [%0], [%1], 16;" :: "r"(dst), "l"(src))
#define CP_ASYNC_COMMIT() asm volatile("cp.async.commit_group;" ::: "memory")
#define CP_ASYNC_WAIT(n)  asm volatile("cp.async.wait_group %0;" :: "n"(n) : "memory")

#define LDSM_X4(r0, r1, r2, r3, addr) \
    asm volatile("ldmatrix.sync.aligned.m8n8.x4.shared.b16 {%0,%1,%2,%3}, [%4];" \
                 : "=r"(r0), "=r"(r1), "=r"(r2), "=r"(r3) : "r"(addr))
#define LDSM_X4_T(r0, r1, r2, r3, addr) \
    asm volatile("ldmatrix.sync.aligned.m8n8.x4.trans.shared.b16 {%0,%1,%2,%3}, [%4];" \
                 : "=r"(r0), "=r"(r1), "=r"(r2), "=r"(r3) : "r"(addr))

__device__ __forceinline__ void mma_bf16(float* c, const uint32_t* a, uint32_t b0, uint32_t b1) {
    asm volatile(
        "mma.sync.aligned.m16n8k16.row.col.f32.bf16.bf16.f32 "
        "{%0,%1,%2,%3}, {%4,%5,%6,%7}, {%8,%9}, {%0,%1,%2,%3};"
        : "+f"(c[0]), "+f"(c[1]), "+f"(c[2]), "+f"(c[3])
        : "r"(a[0]), "r"(a[1]), "r"(a[2]), "r"(a[3]), "r"(b0), "r"(b1));
}

// split two floats into packed bf16 hi pair + lo pair
__device__ __forceinline__ void split2(float x, float y, uint32_t& hi, uint32_t& lo) {
    __nv_bfloat162 h2 = __floats2bfloat162_rn(x, y);
    float2 hf = __bfloat1622float2(h2);
    __nv_bfloat162 l2 = __floats2bfloat162_rn(x - hf.x, y - hf.y);
    hi = *(uint32_t*)&h2;
    lo = *(uint32_t*)&l2;
}

// ---------------- prep kernels ----------------
__global__ void prep_tables_kernel() {
    int t = blockIdx.x * 2 + (threadIdx.x >> 5);
    int i = threadIdx.x & 31;
    float inv = (float)pow(10000.0, -(double)i / 32.0);
    float f = (float)t * inv;
    g_cos[t * 32 + i] = cosf(f);
    g_sin[t * 32 + i] = sinf(f);
}

__global__ void prep_lambda_kernel(const float* __restrict__ lq1, const float* __restrict__ lk1,
                                   const float* __restrict__ lq2, const float* __restrict__ lk2) {
    __shared__ float s1[64], s2[64];
    int i = threadIdx.x;
    s1[i] = lq1[i] * lk1[i];
    s2[i] = lq2[i] * lk2[i];
    __syncthreads();
    if (i == 0) {
        float a = 0.f, b = 0.f;
        for (int j = 0; j < 64; j++) { a += s1[j]; b += s2[j]; }
        g_lambda = expf(a) - expf(b) + LAMBDA_INIT_F;
    }
}

// ---------------- transpose + split all 4 weights (fused) ----------------
__global__ void transpose_split_kernel(const float* __restrict__ Wq, const float* __restrict__ Wk,
                                       const float* __restrict__ Wv, const float* __restrict__ Wo) {
    __shared__ float t[32][33];
    int w = blockIdx.z;
    const float* W = (w == 0) ? Wq : (w == 1) ? Wk : (w == 2) ? Wv : Wo;
    __nv_bfloat16* hi = g_Wt_hi[w];
    __nv_bfloat16* lo = g_Wt_lo[w];
    int k0 = blockIdx.x * 32, n0 = blockIdx.y * 32;
    int tx = threadIdx.x, ty = threadIdx.y;   // 32 x 8
    #pragma unroll
    for (int j = 0; j < 32; j += 8)
        t[ty + j][tx] = W[(size_t)(k0 + ty + j) * E_ + n0 + tx];
    __syncthreads();
    #pragma unroll
    for (int j = 0; j < 32; j += 8) {
        float v = t[tx][ty + j];
        size_t o = (size_t)(n0 + ty + j) * E_ + k0 + tx;
        __nv_bfloat16 h = __float2bfloat16(v);
        hi[o] = h;
        lo[o] = __float2bfloat16(v - __bfloat162float(h));
    }
}

// ---------------- split x into bf16 hi/lo ----------------
__global__ void split_x_kernel(const float* __restrict__ x) {
    size_t i = (size_t)blockIdx.x * 256 + threadIdx.x;
    float v = x[i];
    __nv_bfloat16 h = __float2bfloat16(v);
    g_xhi[i] = h;
    g_xlo[i] = __float2bfloat16(v - __bfloat162float(h));
}

// ---------------- mma.sync bf16 3-term GEMM: C = A @ B^T ----------------
// 512 threads, 16 warps (4m x 4n), warp tile m32 n32. BM=128 BN=128 BK=32.
// 3-stage cp.async, one __syncthreads per K-iter.
// fused==1: epilogue applies RoPE (msel 0,1) / plain (msel 2) + hi/lo bf16 split
//           and writes g_{Q,K,V}bf. fused==0: plain fp32 write to C.
#define GS_BYTES 40960   // per stage: Ahi 10240 | Alo 10240 | Bhi 10240 | Blo 10240

__global__ __launch_bounds__(512, 1) void mma_gemm_kernel(
    const __nv_bfloat16* __restrict__ Ahi, const __nv_bfloat16* __restrict__ Alo,
    const __nv_bfloat16* __restrict__ BhiBase, const __nv_bfloat16* __restrict__ BloBase,
    float* __restrict__ C, int sel_base, int fused)
{
    extern __shared__ char smem[];
    uint32_t sb = smem_u32(smem);
    int tid = threadIdx.x, lane = tid & 31, wid = tid >> 5;
    int mw = wid >> 2, nw = wid & 3;
    int msel = blockIdx.x >> 4;
    int sel = sel_base + msel;
    const __nv_bfloat16* Bhi = BhiBase + (size_t)sel * E_ * E_;
    const __nv_bfloat16* Blo = BloBase + (size_t)sel * E_ * E_;
    int m0 = blockIdx.y * 128, n0 = (blockIdx.x & 15) * 128;

    auto load_stage = [&](int it) {
        int s = it % 3;
        int k0 = it * 32;
        uint32_t st = sb + s * GS_BYTES;
        #pragma unroll
        for (int c = tid; c < 2048; c += 512) {
            int mat = c >> 10;            // 0=A, 1=B
            int cc = c & 1023;
            int p = cc >> 9;              // 0=hi, 1=lo
            int r = (cc >> 2) & 127;
            int ch = cc & 3;
            const __nv_bfloat16* src =
                (mat ? (p ? Blo : Bhi) + (size_t)(n0 + r) * 2048
                     : (p ? Alo : Ahi) + (size_t)(m0 + r) * 2048) + k0 + ch * 8;
            uint32_t dst = st + mat * 20480 + p * 10240 + r * 80 + ch * 16;
            CP_ASYNC16(dst, src);
        }
        CP_ASYNC_COMMIT();
    };

    float acc[2][4][4];
    #pragma unroll
    for (int m = 0; m < 2; m++)
        #pragma unroll
        for (int n = 0; n < 4; n++)
            #pragma unroll
            for (int e = 0; e < 4; e++) acc[m][n][e] = 0.f;

    load_stage(0);
    load_stage(1);

    int krow = lane & 7;
    uint32_t kboff = (lane >> 3) * 16;
    int arow = (lane & 7) + ((lane >> 3) & 1) * 8;
    uint32_t aboff = ((lane >> 4) & 1) * 16;

    for (int it = 0; it < 64; it++) {
        int s = it % 3;
        if (it < 63) CP_ASYNC_WAIT(1);
        else         CP_ASYNC_WAIT(0);
        __syncthreads();
        if (it + 2 < 64) load_stage(it + 2);

        uint32_t sA = sb + s * GS_BYTES;
        uint32_t sB = sA + 20480;

        uint32_t bh[4][4], bl[4][4];
        #pragma unroll
        for (int n = 0; n < 4; n++) {
            uint32_t ra = (uint32_t)(nw * 32 + n * 8 + krow) * 80 + kboff;
            LDSM_X4(bh[n][0], bh[n][1], bh[n][2], bh[n][3], sB + ra);
            LDSM_X4(bl[n][0], bl[n][1], bl[n][2], bl[n][3], sB + 10240 + ra);
        }

        #pragma unroll
        for (int kc = 0; kc < 2; kc++) {
            uint32_t ah[2][4], al[2][4];
            #pragma unroll
            for (int m = 0; m < 2; m++) {
                uint32_t ra = (uint32_t)(mw * 32 + m * 16 + arow) * 80 + aboff + kc * 32;
                LDSM_X4(ah[m][0], ah[m][1], ah[m][2], ah[m][3], sA + ra);
                LDSM_X4(al[m][0], al[m][1], al[m][2], al[m][3], sA + 10240 + ra);
            }
            #pragma unroll
            for (int t = 0; t < 3; t++)
                #pragma unroll
                for (int m = 0; m < 2; m++)
                    #pragma unroll
                    for (int n = 0; n < 4; n++) {
                        const uint32_t* a = (t == 1) ? al[m] : ah[m];
                        uint32_t b0 = (t == 2) ? bl[n][2 * kc]     : bh[n][2 * kc];
                        uint32_t b1 = (t == 2) ? bl[n][2 * kc + 1] : bh[n][2 * kc + 1];
                        mma_bf16(acc[m][n], a, b0, b1);
                    }
        }
    }

    if (!fused) {
        #pragma unroll
        for (int m = 0; m < 2; m++) {
            size_t r0 = m0 + mw * 32 + m * 16 + (lane >> 2);
            #pragma unroll
            for (int n = 0; n < 4; n++) {
                size_t col = n0 + nw * 32 + n * 8 + 2 * (lane & 3);
                *(float2*)&C[r0 * 2048 + col]       = make_float2(acc[m][n][0], acc[m][n][1]);
                *(float2*)&C[(r0 + 8) * 2048 + col] = make_float2(acc[m][n][2], acc[m][n][3]);
            }
        }
    } else {
        __nv_bfloat16* dh = (msel == 0) ? g_Qbf[0] : (msel == 1) ? g_Kbf[0] : g_Vbf[0];
        __nv_bfloat16* dl = (msel == 0) ? g_Qbf[1] : (msel == 1) ? g_Kbf[1] : g_Vbf[1];
        bool rope = (msel < 2);
        #pragma unroll
        for (int m = 0; m < 2; m++) {
            int r0 = m0 + mw * 32 + m * 16 + (lane >> 2);
            int r1 = r0 + 8;
            int s0 = r0 & (S_ - 1), s1 = r1 & (S_ - 1);
            #pragma unroll
            for (int n = 0; n < 4; n++) {
                int col = n0 + nw * 32 + n * 8 + 2 * (lane & 3);   // even
                float v0 = acc[m][n][0], v1 = acc[m][n][1];
                float v2 = acc[m][n][2], v3 = acc[m][n][3];
                if (rope) {
                    int i = (col & 63) >> 1;
                    float c0 = g_cos[s0 * 32 + i], sn0 = g_sin[s0 * 32 + i];
                    float c1 = g_cos[s1 * 32 + i], sn1 = g_sin[s1 * 32 + i];
                    float t0 = v0 * c0 - v1 * sn0;
                    float t1 = v0 * sn0 + v1 * c0;
                    v0 = t0; v1 = t1;
                    t0 = v2 * c1 - v3 * sn1;
                    t1 = v2 * sn1 + v3 * c1;
                    v2 = t0; v3 = t1;
                }
                uint32_t hi0, lo0, hi1, lo1;
                split2(v0, v1, hi0, lo0);
                split2(v2, v3, hi1, lo1);
                size_t o0 = (size_t)r0 * 2048 + col;
                size_t o1 = (size_t)r1 * 2048 + col;
                *(uint32_t*)&dh[o0] = hi0;
                *(uint32_t*)&dl[o0] = lo0;
                *(uint32_t*)&dh[o1] = hi1;
                *(uint32_t*)&dl[o1] = lo1;
            }
        }
    }
}

// ---------------- flash attention via mma.sync (bf16 3-term split) ----------------
// 3-stage pipeline, ONE __syncthreads per key-tile.
#define FB_BYTES 71680
#define KREG(buf, ss)  ((buf) * FB_BYTES + (ss) * 9216)
#define VREG(buf, hf)  ((buf) * FB_BYTES + 36864 + (hf) * 17408)

__global__ __launch_bounds__(256) void flash_mma_kernel(const float* __restrict__ lnw) {
    extern __shared__ char smem[];
    uint32_t sb = smem_u32(smem);
    __shared__ float sLn[128];

    int tid = threadIdx.x, lane = tid & 31, wid = tid >> 5;
    int stream = wid >> 2, qw = wid & 3;
    int qt = 31 - blockIdx.x;           // heavy tiles first
    int h = blockIdx.y, b = blockIdx.z;
    int q0 = qt * 64;
    int bS = b * S_;
    if (tid < 128) sLn[tid] = lnw[tid];

    auto load_tile = [&](int kt) {
        int n0 = kt * 64, buf = kt % 3;
        for (int i = tid; i < 4096; i += 256) {
            uint32_t dst;
            const __nv_bfloat16* src;
            if (i < 2048) {
                int ss = i >> 9, r = (i >> 3) & 63, c = i & 7;
                dst = sb + KREG(buf, ss) + r * 144 + c * 16;
                src = &g_Kbf[ss & 1][(((size_t)(bS + n0 + r) * 32 + 2 * h + (ss >> 1)) << 6) + c * 8];
            } else {
                int j = i - 2048;
                int hf = j >> 10, r = (j >> 4) & 63, c = j & 15;
                dst = sb + VREG(buf, hf) + r * 272 + c * 16;
                src = &g_Vbf[hf][(((size_t)(bS + n0 + r) * 16 + h) << 7) + c * 8];
            }
            CP_ASYNC16(dst, src);
        }
        CP_ASYNC_COMMIT();
    };

    // ---- stage Q into buffer 2's K region, plus prefetch tiles 0,1 ----
    for (int i = tid; i < 2048; i += 256) {
        int ss = i >> 9, r = (i >> 3) & 63, c = i & 7;
        uint32_t dst = sb + KREG(2, ss) + r * 144 + c * 16;
        const __nv_bfloat16* src =
            &g_Qbf[ss & 1][(((size_t)(bS + q0 + r) * 32 + 2 * h + (ss >> 1)) << 6) + c * 8];
        CP_ASYNC16(dst, src);
    }
    CP_ASYNC_COMMIT();
    load_tile(0);
    if (qt >= 1) { load_tile(1); CP_ASYNC_WAIT(1); }
    else         { CP_ASYNC_WAIT(0); }
    __syncthreads();

    uint32_t qh[4][4], ql[4][4];
    {
        int row = qw * 16 + (lane & 7) + ((lane >> 3) & 1) * 8;
        uint32_t boff = ((lane >> 4) & 1) * 16;
        uint32_t bh_ = sb + KREG(2, stream * 2 + 0) + row * 144 + boff;
        uint32_t bl_ = sb + KREG(2, stream * 2 + 1) + row * 144 + boff;
        #pragma unroll
        for (int kc = 0; kc < 4; kc++) {
            LDSM_X4(qh[kc][0], qh[kc][1], qh[kc][2], qh[kc][3], bh_ + kc * 32);
            LDSM_X4(ql[kc][0], ql[kc][1], ql[kc][2], ql[kc][3], bl_ + kc * 32);
        }
    }

    float out[16][4];
    #pragma unroll
    for (int i = 0; i < 16; i++)
        #pragma unroll
        for (int e = 0; e < 4; e++) out[i][e] = 0.f;
    float m0 = -1e30f, m1 = -1e30f, l0 = 0.f, l1 = 0.f;

    int krow = lane & 7;
    uint32_t kboff = (lane >> 3) * 16;
    int vrow = (lane & 7) + ((lane >> 3) & 1) * 8;
    uint32_t vboff = ((lane >> 4) & 1) * 16;

    for (int kt = 0; kt <= qt; kt++) {
        int buf = kt % 3;
        if (kt < qt) CP_ASYNC_WAIT(1);
        else         CP_ASYNC_WAIT(0);
        __syncthreads();
        if (kt + 2 <= qt) load_tile(kt + 2);

        // ---- scores S = Q K^T, rotating acc targets ----
        float sacc[8][4];
        #pragma unroll
        for (int nt = 0; nt < 8; nt++)
            #pragma unroll
            for (int e = 0; e < 4; e++) sacc[nt][e] = 0.f;

        uint32_t kbh = sb + KREG(buf, stream * 2 + 0);
        uint32_t kbl = sb + KREG(buf, stream * 2 + 1);

        #pragma unroll
        for (int np = 0; np < 4; np++) {
            int ntA = 2 * np, ntB = ntA + 1;
            uint32_t bhA[8], blA[8], bhB[8], blB[8];
            uint32_t raA = (uint32_t)(ntA * 8 + krow) * 144 + kboff;
            uint32_t raB = (uint32_t)(ntB * 8 + krow) * 144 + kboff;
            LDSM_X4(bhA[0], bhA[1], bhA[2], bhA[3], kbh + raA);
            LDSM_X4(bhA[4], bhA[5], bhA[6], bhA[7], kbh + raA + 64);
            LDSM_X4(bhB[0], bhB[1], bhB[2], bhB[3], kbh + raB);
            LDSM_X4(bhB[4], bhB[5], bhB[6], bhB[7], kbh + raB + 64);
            LDSM_X4(blA[0], blA[1], blA[2], blA[3], kbl + raA);
            LDSM_X4(blA[4], blA[5], blA[6], blA[7], kbl + raA + 64);
            LDSM_X4(blB[0], blB[1], blB[2], blB[3], kbl + raB);
            LDSM_X4(blB[4], blB[5], blB[6], blB[7], kbl + raB + 64);
            float tA[4] = {0.f, 0.f, 0.f, 0.f}, tB[4] = {0.f, 0.f, 0.f, 0.f};
            #pragma unroll
            for (int t = 0; t < 3; t++) {
                #pragma unroll
                for (int kc = 0; kc < 4; kc++) {
                    const uint32_t* a = (t == 1) ? ql[kc] : qh[kc];
                    float* dA = (kc & 1) ? tA : sacc[ntA];
                    float* dB = (kc & 1) ? tB : sacc[ntB];
                    uint32_t bA0 = (t == 2) ? blA[2 * kc] : bhA[2 * kc];
                    uint32_t bA1 = (t == 2) ? blA[2 * kc + 1] : bhA[2 * kc + 1];
                    uint32_t bB0 = (t == 2) ? blB[2 * kc] : bhB[2 * kc];
                    uint32_t bB1 = (t == 2) ? blB[2 * kc + 1] : bhB[2 * kc + 1];
                    mma_bf16(dA, a, bA0, bA1);
                    mma_bf16(dB, a, bB0, bB1);
                }
            }
            #pragma unroll
            for (int e = 0; e < 4; e++) { sacc[ntA][e] += tA[e]; sacc[ntB][e] += tB[e]; }
        }

        // ---- online softmax (2 rows per thread) ----
        bool diag = (kt == qt);
        int rlo0 = qw * 16 + (lane >> 2);
        float rm0 = -1e30f, rm1 = -1e30f;
        #pragma unroll
        for (int nt = 0; nt < 8; nt++) {
            #pragma unroll
            for (int e = 0; e < 4; e++) {
                float s = sacc[nt][e] * 0.125f;
                if (diag) {
                    int colL = nt * 8 + 2 * (lane & 3) + (e & 1);
                    int rowL = rlo0 + ((e >> 1) << 3);
                    if (colL > rowL) s = -1e30f;
                }
                sacc[nt][e] = s;
                if (e < 2) rm0 = fmaxf(rm0, s); else rm1 = fmaxf(rm1, s);
            }
        }
        #pragma unroll
        for (int w = 1; w < 4; w <<= 1) {
            rm0 = fmaxf(rm0, __shfl_xor_sync(0xffffffffu, rm0, w));
            rm1 = fmaxf(rm1, __shfl_xor_sync(0xffffffffu, rm1, w));
        }
        float nm0 = fmaxf(m0, rm0), nm1 = fmaxf(m1, rm1);
        float c0 = __expf(m0 - nm0), c1 = __expf(m1 - nm1);
        float ps0 = 0.f, ps1 = 0.f;
        #pragma unroll
        for (int nt = 0; nt < 8; nt++) {
            float p0 = __expf(sacc[nt][0] - nm0);
            float p1 = __expf(sacc[nt][1] - nm0);
            float p2 = __expf(sacc[nt][2] - nm1);
            float p3 = __expf(sacc[nt][3] - nm1);
            sacc[nt][0] = p0; sacc[nt][1] = p1; sacc[nt][2] = p2; sacc[nt][3] = p3;
            ps0 += p0 + p1; ps1 += p2 + p3;
        }
        #pragma unroll
        for (int w = 1; w < 4; w <<= 1) {
            ps0 += __shfl_xor_sync(0xffffffffu, ps0, w);
            ps1 += __shfl_xor_sync(0xffffffffu, ps1, w);
        }
        l0 = l0 * c0 + ps0;
        l1 = l1 * c1 + ps1;
        m0 = nm0; m1 = nm1;
        #pragma unroll
        for (int nt = 0; nt < 16; nt++) {
            out[nt][0] *= c0; out[nt][1] *= c0;
            out[nt][2] *= c1; out[nt][3] *= c1;
        }

        // ---- PV, rotating acc targets ----
        uint32_t vbh = sb + VREG(buf, 0);
        uint32_t vbl = sb + VREG(buf, 1);
        #pragma unroll
        for (int kc2 = 0; kc2 < 4; kc2++) {
            uint32_t pah[4], pal[4];
            split2(sacc[2 * kc2][0], sacc[2 * kc2][1], pah[0], pal[0]);
            split2(sacc[2 * kc2][2], sacc[2 * kc2][3], pah[1], pal[1]);
            split2(sacc[2 * kc2 + 1][0], sacc[2 * kc2 + 1][1], pah[2], pal[2]);
            split2(sacc[2 * kc2 + 1][2], sacc[2 * kc2 + 1][3], pah[3], pal[3]);
            uint32_t vra = (uint32_t)(kc2 * 16 + vrow) * 272 + vboff;
            #pragma unroll
            for (int dpp = 0; dpp < 4; dpp++) {
                int dp0 = 2 * dpp, dp1 = dp0 + 1;
                uint32_t vh0[4], vl0[4], vh1[4], vl1[4];
                LDSM_X4_T(vh0[0], vh0[1], vh0[2], vh0[3], vbh + vra + dp0 * 32);
                LDSM_X4_T(vh1[0], vh1[1], vh1[2], vh1[3], vbh + vra + dp1 * 32);
                LDSM_X4_T(vl0[0], vl0[1], vl0[2], vl0[3], vbl + vra + dp0 * 32);
                LDSM_X4_T(vl1[0], vl1[1], vl1[2], vl1[3], vbl + vra + dp1 * 32);
                #pragma unroll
                for (int t = 0; t < 3; t++) {
                    const uint32_t* p = (t == 1) ? pal : pah;
                    const uint32_t* A0 = (t == 2) ? vl0 : vh0;
                    const uint32_t* A1 = (t == 2) ? vl1 : vh1;
                    mma_bf16(out[2 * dp0],     p, A0[0], A0[1]);
                    mma_bf16(out[2 * dp0 + 1], p, A0[2], A0[3]);
                    mma_bf16(out[2 * dp1],     p, A1[0], A1[1]);
                    mma_bf16(out[2 * dp1 + 1], p, A1[2], A1[3]);
                }
            }
        }
    }

    // ---- epilogue: diff across streams, RMS norm, split-write g_Ahi/g_Alo ----
    float inv0 = 1.f / l0, inv1 = 1.f / l1;
    int r0 = qw * 16 + (lane >> 2);
    float* sX = (float*)smem;
    __syncthreads();
    if (stream == 1) {
        #pragma unroll
        for (int nt = 0; nt < 16; nt++) {
            int col = nt * 8 + 2 * (lane & 3);
            sX[r0 * 132 + col]           = out[nt][0] * inv0;
            sX[r0 * 132 + col + 1]       = out[nt][1] * inv0;
            sX[(r0 + 8) * 132 + col]     = out[nt][2] * inv1;
            sX[(r0 + 8) * 132 + col + 1] = out[nt][3] * inv1;
        }
    }
    __syncthreads();
    if (stream == 0) {
        float lam = g_lambda;
        float ss0 = 0.f, ss1 = 0.f;
        #pragma unroll
        for (int nt = 0; nt < 16; nt++) {
            int col = nt * 8 + 2 * (lane & 3);
            out[nt][0] = out[nt][0] * inv0 - lam * sX[r0 * 132 + col];
            out[nt][1] = out[nt][1] * inv0 - lam * sX[r0 * 132 + col + 1];
            out[nt][2] = out[nt][2] * inv1 - lam * sX[(r0 + 8) * 132 + col];
            out[nt][3] = out[nt][3] * inv1 - lam * sX[(r0 + 8) * 132 + col + 1];
            ss0 += out[nt][0] * out[nt][0] + out[nt][1] * out[nt][1];
            ss1 += out[nt][2] * out[nt][2] + out[nt][3] * out[nt][3];
        }
        #pragma unroll
        for (int w = 1; w < 4; w <<= 1) {
            ss0 += __shfl_xor_sync(0xffffffffu, ss0, w);
            ss1 += __shfl_xor_sync(0xffffffffu, ss1, w);
        }
        float rms0 = rsqrtf(ss0 * (1.f / 128.f) + 1e-5f);
        float rms1 = rsqrtf(ss1 * (1.f / 128.f) + 1e-5f);
        #pragma unroll
        for (int nt = 0; nt < 16; nt++) {
            int col = nt * 8 + 2 * (lane & 3);
            size_t ga = ((size_t)(bS + q0 + r0)) * 2048 + h * 128 + col;
            size_t gb = ((size_t)(bS + q0 + r0 + 8)) * 2048 + h * 128 + col;
            float v0 = out[nt][0] * rms0 * sLn[col] * OUT_SCALE_F;
            float v1 = out[nt][1] * rms0 * sLn[col + 1] * OUT_SCALE_F;
            float v2 = out[nt][2] * rms1 * sLn[col] * OUT_SCALE_F;
            float v3 = out[nt][3] * rms1 * sLn[col + 1] * OUT_SCALE_F;
            uint32_t hi0, lo0, hi1, lo1;
            split2(v0, v1, hi0, lo0);
            split2(v2, v3, hi1, lo1);
            *(uint32_t*)&g_Ahi[ga] = hi0;
            *(uint32_t*)&g_Alo[ga] = lo0;
            *(uint32_t*)&g_Ahi[gb] = hi1;
            *(uint32_t*)&g_Alo[gb] = lo1;
        }
    }
}

// ---------------- launch ----------------
extern "C" void kernel_launch(void* const* d_in, const int* in_sizes, int n_in,
                              void* d_out, int out_size) {
    const float* x   = (const float*)d_in[0];
    const float* Wq  = (const float*)d_in[1];
    const float* Wk  = (const float*)d_in[2];
    const float* Wv  = (const float*)d_in[3];
    const float* Wo  = (const float*)d_in[4];
    const float* lq1 = (const float*)d_in[5];
    const float* lk1 = (const float*)d_in[6];
    const float* lq2 = (const float*)d_in[7];
    const float* lk2 = (const float*)d_in[8];
    const float* lnw = (const float*)d_in[9];
    float* out = (float*)d_out;

    __nv_bfloat16 *xhi, *xlo, *Ahi, *Alo, *Wth, *Wtl;
    cudaGetSymbolAddress((void**)&xhi, g_xhi);
    cudaGetSymbolAddress((void**)&xlo, g_xlo);
    cudaGetSymbolAddress((void**)&Ahi, g_Ahi);
    cudaGetSymbolAddress((void**)&Alo, g_Alo);
    cudaGetSymbolAddress((void**)&Wth, g_Wt_hi);
    cudaGetSymbolAddress((void**)&Wtl, g_Wt_lo);

    cudaFuncSetAttribute(flash_mma_kernel, cudaFuncAttributeMaxDynamicSharedMemorySize,
                         3 * FB_BYTES);
    cudaFuncSetAttribute(mma_gemm_kernel, cudaFuncAttributeMaxDynamicSharedMemorySize,
                         3 * GS_BYTES);

    // launch order arranged so ncu (-s 5 -c 1) captures flash_mma_kernel (#6)
    prep_tables_kernel<<<1024, 64>>>();                                   // 1
    prep_lambda_kernel<<<1, 64>>>(lq1, lk1, lq2, lk2);                    // 2
    dim3 tg(E_ / 32, E_ / 32, 4), tb(32, 8);
    transpose_split_kernel<<<tg, tb>>>(Wq, Wk, Wv, Wo);                   // 3
    split_x_kernel<<<((size_t)ROWS_ * E_) / 256, 256>>>(x);               // 4

    size_t gsmem = 3 * GS_BYTES;
    dim3 gqkv(48, ROWS_ / 128);
    mma_gemm_kernel<<<gqkv, 512, gsmem>>>(xhi, xlo, Wth, Wtl, nullptr, 0, 1);  // 5

    dim3 fg(32, 16, 2);
    flash_mma_kernel<<<fg, 256, 3 * FB_BYTES>>>(lnw);                     // 6  <- profiled

    dim3 go(16, ROWS_ / 128);
    mma_gemm_kernel<<<go, 512, gsmem>>>(Ahi, Alo, Wth, Wtl, out, 3, 0);   // 7
}

// round 8
// speedup vs baseline: 5.4357x; 1.1138x over previous
#include <cuda_runtime.h>
#include <cuda_bf16.h>
#include <cstdint>

#define B_ 2
#define S_ 2048
#define E_ 2048
#define H_ 16
#define HD_ 64
#define ROWS_ (B_ * S_)          // 4096
#define LAMBDA_INIT_F 0.783605766532f
#define OUT_SCALE_F   0.216394233468f   // 1 - LAMBDA_INIT

// ---------------- scratch (device globals; no allocations) ----------------
__device__ __nv_bfloat16 g_xhi[(size_t)ROWS_ * E_];
__device__ __nv_bfloat16 g_xlo[(size_t)ROWS_ * E_];
__device__ __nv_bfloat16 g_Ahi[(size_t)ROWS_ * E_];   // flash output split
__device__ __nv_bfloat16 g_Alo[(size_t)ROWS_ * E_];
__device__ __nv_bfloat16 g_Wt_hi[4][(size_t)E_ * E_]; // transposed weights [n][k]: q,k,v,o
__device__ __nv_bfloat16 g_Wt_lo[4][(size_t)E_ * E_];
__device__ __nv_bfloat16 g_Qbf[2][(size_t)ROWS_ * E_];  // [half][row*2048 + head*64 + d] post-rope
__device__ __nv_bfloat16 g_Kbf[2][(size_t)ROWS_ * E_];
__device__ __nv_bfloat16 g_Vbf[2][(size_t)ROWS_ * E_];  // [half][row*2048 + h*128 + d]
__device__ float g_cos[S_ * 32];
__device__ float g_sin[S_ * 32];
__device__ float g_lambda;

// ---------------- small helpers ----------------
__device__ __forceinline__ uint32_t smem_u32(const void* p) {
    uint32_t a;
    asm("{ .reg .u64 t; cvta.to.shared.u64 t, %1; cvt.u32.u64 %0, t; }" : "=r"(a) : "l"(p));
    return a;
}
#define CP_ASYNC16(dst, src) \
    asm volatile("cp.async.cg.shared.global [%0], [%1], 16;" :: "r"(dst), "l"(src))
#define CP_ASYNC_COMMIT() asm volatile("cp.async.commit_group;" ::: "memory")
#define CP_ASYNC_WAIT(n)  asm volatile("cp.async.wait_group %0;" :: "n"(n) : "memory")

#define LDSM_X4(r0, r1, r2, r3, addr) \
    asm volatile("ldmatrix.sync.aligned.m8n8.x4.shared.b16 {%0,%1,%2,%3}, [%4];" \
                 : "=r"(r0), "=r"(r1), "=r"(r2), "=r"(r3) : "r"(addr))
#define LDSM_X4_T(r0, r1, r2, r3, addr) \
    asm volatile("ldmatrix.sync.aligned.m8n8.x4.trans.shared.b16 {%0,%1,%2,%3}, [%4];" \
                 : "=r"(r0), "=r"(r1), "=r"(r2), "=r"(r3) : "r"(addr))

__device__ __forceinline__ void mma_bf16(float* c, const uint32_t* a, uint32_t b0, uint32_t b1) {
    asm volatile(
        "mma.sync.aligned.m16n8k16.row.col.f32.bf16.bf16.f32 "
        "{%0,%1,%2,%3}, {%4,%5,%6,%7}, {%8,%9}, {%0,%1,%2,%3};"
        : "+f"(c[0]), "+f"(c[1]), "+f"(c[2]), "+f"(c[3])
        : "r"(a[0]), "r"(a[1]), "r"(a[2]), "r"(a[3]), "r"(b0), "r"(b1));
}

// split two floats into packed bf16 hi pair + lo pair
__device__ __forceinline__ void split2(float x, float y, uint32_t& hi, uint32_t& lo) {
    __nv_bfloat162 h2 = __floats2bfloat162_rn(x, y);
    float2 hf = __bfloat1622float2(h2);
    __nv_bfloat162 l2 = __floats2bfloat162_rn(x - hf.x, y - hf.y);
    hi = *(uint32_t*)&h2;
    lo = *(uint32_t*)&l2;
}

// ---------------- prep: rope tables + lambda (merged, launch #1) ----------------
__global__ void prep_all_kernel(const float* __restrict__ lq1, const float* __restrict__ lk1,
                                const float* __restrict__ lq2, const float* __restrict__ lk2) {
    if (blockIdx.x < 1024) {
        int t = blockIdx.x * 2 + (threadIdx.x >> 5);
        int i = threadIdx.x & 31;
        float inv = (float)pow(10000.0, -(double)i / 32.0);
        float f = (float)t * inv;
        g_cos[t * 32 + i] = cosf(f);
        g_sin[t * 32 + i] = sinf(f);
    } else {
        __shared__ float s1[64], s2[64];
        int i = threadIdx.x;
        s1[i] = lq1[i] * lk1[i];
        s2[i] = lq2[i] * lk2[i];
        __syncthreads();
        if (i == 0) {
            float a = 0.f, b = 0.f;
            for (int j = 0; j < 64; j++) { a += s1[j]; b += s2[j]; }
            g_lambda = expf(a) - expf(b) + LAMBDA_INIT_F;
        }
    }
}

// ---------------- preprocess: 4 weight transposes + x split (merged, launch #2) ----------------
// blocks [0,16384): transpose+split weight tiles; blocks [16384,49152): split x
__global__ __launch_bounds__(256) void preprocess_kernel(
    const float* __restrict__ x,
    const float* __restrict__ Wq, const float* __restrict__ Wk,
    const float* __restrict__ Wv, const float* __restrict__ Wo) {
    int bx = blockIdx.x;
    if (bx < 16384) {
        __shared__ float t[32][33];
        int w = bx >> 12;
        const float* W = (w == 0) ? Wq : (w == 1) ? Wk : (w == 2) ? Wv : Wo;
        __nv_bfloat16* hi = g_Wt_hi[w];
        __nv_bfloat16* lo = g_Wt_lo[w];
        int t2 = bx & 4095;
        int k0 = (t2 & 63) * 32, n0 = (t2 >> 6) * 32;
        int tx = threadIdx.x & 31, ty = threadIdx.x >> 5;   // 32 x 8
        #pragma unroll
        for (int j = 0; j < 32; j += 8)
            t[ty + j][tx] = W[(size_t)(k0 + ty + j) * E_ + n0 + tx];
        __syncthreads();
        #pragma unroll
        for (int j = 0; j < 32; j += 8) {
            float v = t[tx][ty + j];
            size_t o = (size_t)(n0 + ty + j) * E_ + k0 + tx;
            __nv_bfloat16 h = __float2bfloat16(v);
            hi[o] = h;
            lo[o] = __float2bfloat16(v - __bfloat162float(h));
        }
    } else {
        size_t i = (size_t)(bx - 16384) * 256 + threadIdx.x;
        float v = x[i];
        __nv_bfloat16 h = __float2bfloat16(v);
        g_xhi[i] = h;
        g_xlo[i] = __float2bfloat16(v - __bfloat162float(h));
    }
}

// ---------------- mma.sync bf16 3-term GEMM: C = A @ B^T ----------------
// 512 threads, 16 warps (4m x 4n), warp tile m32 n32. BM=128 BN=128 BK=64.
// 2-stage cp.async, ONE __syncthreads per K-iter (32 iters).
// Stage layout (144B row stride, 128 rows): Ahi | Alo | Bhi | Blo @ 18432B each.
#define GSTAGE 73728

__global__ __launch_bounds__(512, 1) void mma_gemm_kernel(
    const __nv_bfloat16* __restrict__ Ahi, const __nv_bfloat16* __restrict__ Alo,
    const __nv_bfloat16* __restrict__ BhiBase, const __nv_bfloat16* __restrict__ BloBase,
    float* __restrict__ C, int sel_base, int fused)
{
    extern __shared__ char smem[];
    uint32_t sb = smem_u32(smem);
    int tid = threadIdx.x, lane = tid & 31, wid = tid >> 5;
    int mw = wid >> 2, nw = wid & 3;
    int msel = blockIdx.x >> 4;
    int sel = sel_base + msel;
    const __nv_bfloat16* Bhi = BhiBase + (size_t)sel * E_ * E_;
    const __nv_bfloat16* Blo = BloBase + (size_t)sel * E_ * E_;
    int m0 = blockIdx.y * 128, n0 = (blockIdx.x & 15) * 128;

    auto load_stage = [&](int it) {
        int k0 = it * 64;
        uint32_t st = sb + (it & 1) * GSTAGE;
        #pragma unroll
        for (int c = tid; c < 4096; c += 512) {
            int mat = c >> 11;            // 0=A, 1=B
            int cc = c & 2047;
            int p = cc >> 10;             // 0=hi, 1=lo
            int r = (cc >> 3) & 127;
            int ch = c & 7;
            const __nv_bfloat16* src =
                (mat ? (p ? Blo : Bhi) + (size_t)(n0 + r) * 2048
                     : (p ? Alo : Ahi) + (size_t)(m0 + r) * 2048) + k0 + ch * 8;
            uint32_t dst = st + mat * 36864 + p * 18432 + r * 144 + ch * 16;
            CP_ASYNC16(dst, src);
        }
        CP_ASYNC_COMMIT();
    };

    float acc[2][4][4];
    #pragma unroll
    for (int m = 0; m < 2; m++)
        #pragma unroll
        for (int n = 0; n < 4; n++)
            #pragma unroll
            for (int e = 0; e < 4; e++) acc[m][n][e] = 0.f;

    load_stage(0);

    int krow = lane & 7;
    uint32_t kboff = (lane >> 3) * 16;       // k32 coverage per x4
    int arow = (lane & 7) + ((lane >> 3) & 1) * 8;
    uint32_t aboff = ((lane >> 4) & 1) * 16;

    for (int it = 0; it < 32; it++) {
        CP_ASYNC_WAIT(0);
        __syncthreads();
        if (it + 1 < 32) load_stage(it + 1);

        uint32_t sA = sb + (it & 1) * GSTAGE;
        uint32_t sB = sA + 36864;

        #pragma unroll
        for (int kh = 0; kh < 2; kh++) {           // two k32 halves of BK=64
            uint32_t bh[4][4], bl[4][4];
            #pragma unroll
            for (int n = 0; n < 4; n++) {
                uint32_t ra = (uint32_t)(nw * 32 + n * 8 + krow) * 144 + kboff + kh * 64;
                LDSM_X4(bh[n][0], bh[n][1], bh[n][2], bh[n][3], sB + ra);
                LDSM_X4(bl[n][0], bl[n][1], bl[n][2], bl[n][3], sB + 18432 + ra);
            }
            #pragma unroll
            for (int kc2 = 0; kc2 < 2; kc2++) {    // k16 chunks within half
                uint32_t ah[2][4], al[2][4];
                #pragma unroll
                for (int m = 0; m < 2; m++) {
                    uint32_t ra = (uint32_t)(mw * 32 + m * 16 + arow) * 144 + aboff
                                + (kh * 2 + kc2) * 32;
                    LDSM_X4(ah[m][0], ah[m][1], ah[m][2], ah[m][3], sA + ra);
                    LDSM_X4(al[m][0], al[m][1], al[m][2], al[m][3], sA + 18432 + ra);
                }
                #pragma unroll
                for (int t = 0; t < 3; t++)
                    #pragma unroll
                    for (int m = 0; m < 2; m++)
                        #pragma unroll
                        for (int n = 0; n < 4; n++) {
                            const uint32_t* a = (t == 1) ? al[m] : ah[m];
                            uint32_t b0 = (t == 2) ? bl[n][2 * kc2]     : bh[n][2 * kc2];
                            uint32_t b1 = (t == 2) ? bl[n][2 * kc2 + 1] : bh[n][2 * kc2 + 1];
                            mma_bf16(acc[m][n], a, b0, b1);
                        }
            }
        }
    }

    if (!fused) {
        #pragma unroll
        for (int m = 0; m < 2; m++) {
            size_t r0 = m0 + mw * 32 + m * 16 + (lane >> 2);
            #pragma unroll
            for (int n = 0; n < 4; n++) {
                size_t col = n0 + nw * 32 + n * 8 + 2 * (lane & 3);
                *(float2*)&C[r0 * 2048 + col]       = make_float2(acc[m][n][0], acc[m][n][1]);
                *(float2*)&C[(r0 + 8) * 2048 + col] = make_float2(acc[m][n][2], acc[m][n][3]);
            }
        }
    } else {
        __nv_bfloat16* dh = (msel == 0) ? g_Qbf[0] : (msel == 1) ? g_Kbf[0] : g_Vbf[0];
        __nv_bfloat16* dl = (msel == 0) ? g_Qbf[1] : (msel == 1) ? g_Kbf[1] : g_Vbf[1];
        bool rope = (msel < 2);
        #pragma unroll
        for (int m = 0; m < 2; m++) {
            int r0 = m0 + mw * 32 + m * 16 + (lane >> 2);
            int r1 = r0 + 8;
            int s0 = r0 & (S_ - 1), s1 = r1 & (S_ - 1);
            #pragma unroll
            for (int n = 0; n < 4; n++) {
                int col = n0 + nw * 32 + n * 8 + 2 * (lane & 3);   // even
                float v0 = acc[m][n][0], v1 = acc[m][n][1];
                float v2 = acc[m][n][2], v3 = acc[m][n][3];
                if (rope) {
                    int i = (col & 63) >> 1;
                    float c0 = g_cos[s0 * 32 + i], sn0 = g_sin[s0 * 32 + i];
                    float c1 = g_cos[s1 * 32 + i], sn1 = g_sin[s1 * 32 + i];
                    float t0 = v0 * c0 - v1 * sn0;
                    float t1 = v0 * sn0 + v1 * c0;
                    v0 = t0; v1 = t1;
                    t0 = v2 * c1 - v3 * sn1;
                    t1 = v2 * sn1 + v3 * c1;
                    v2 = t0; v3 = t1;
                }
                uint32_t hi0, lo0, hi1, lo1;
                split2(v0, v1, hi0, lo0);
                split2(v2, v3, hi1, lo1);
                size_t o0 = (size_t)r0 * 2048 + col;
                size_t o1 = (size_t)r1 * 2048 + col;
                *(uint32_t*)&dh[o0] = hi0;
                *(uint32_t*)&dl[o0] = lo0;
                *(uint32_t*)&dh[o1] = hi1;
                *(uint32_t*)&dl[o1] = lo1;
            }
        }
    }
}

// ---------------- flash attention via mma.sync (bf16 3-term split) ----------------
// 3-stage pipeline, ONE __syncthreads per key-tile.
#define FB_BYTES 71680
#define KREG(buf, ss)  ((buf) * FB_BYTES + (ss) * 9216)
#define VREG(buf, hf)  ((buf) * FB_BYTES + 36864 + (hf) * 17408)

__global__ __launch_bounds__(256) void flash_mma_kernel(const float* __restrict__ lnw) {
    extern __shared__ char smem[];
    uint32_t sb = smem_u32(smem);
    __shared__ float sLn[128];

    int tid = threadIdx.x, lane = tid & 31, wid = tid >> 5;
    int stream = wid >> 2, qw = wid & 3;
    int qt = 31 - blockIdx.x;           // heavy tiles first
    int h = blockIdx.y, b = blockIdx.z;
    int q0 = qt * 64;
    int bS = b * S_;
    if (tid < 128) sLn[tid] = lnw[tid];

    auto load_tile = [&](int kt) {
        int n0 = kt * 64, buf = kt % 3;
        for (int i = tid; i < 4096; i += 256) {
            uint32_t dst;
            const __nv_bfloat16* src;
            if (i < 2048) {
                int ss = i >> 9, r = (i >> 3) & 63, c = i & 7;
                dst = sb + KREG(buf, ss) + r * 144 + c * 16;
                src = &g_Kbf[ss & 1][(((size_t)(bS + n0 + r) * 32 + 2 * h + (ss >> 1)) << 6) + c * 8];
            } else {
                int j = i - 2048;
                int hf = j >> 10, r = (j >> 4) & 63, c = j & 15;
                dst = sb + VREG(buf, hf) + r * 272 + c * 16;
                src = &g_Vbf[hf][(((size_t)(bS + n0 + r) * 16 + h) << 7) + c * 8];
            }
            CP_ASYNC16(dst, src);
        }
        CP_ASYNC_COMMIT();
    };

    // ---- stage Q into buffer 2's K region, plus prefetch tiles 0,1 ----
    for (int i = tid; i < 2048; i += 256) {
        int ss = i >> 9, r = (i >> 3) & 63, c = i & 7;
        uint32_t dst = sb + KREG(2, ss) + r * 144 + c * 16;
        const __nv_bfloat16* src =
            &g_Qbf[ss & 1][(((size_t)(bS + q0 + r) * 32 + 2 * h + (ss >> 1)) << 6) + c * 8];
        CP_ASYNC16(dst, src);
    }
    CP_ASYNC_COMMIT();
    load_tile(0);
    if (qt >= 1) { load_tile(1); CP_ASYNC_WAIT(1); }
    else         { CP_ASYNC_WAIT(0); }
    __syncthreads();

    uint32_t qh[4][4], ql[4][4];
    {
        int row = qw * 16 + (lane & 7) + ((lane >> 3) & 1) * 8;
        uint32_t boff = ((lane >> 4) & 1) * 16;
        uint32_t bh_ = sb + KREG(2, stream * 2 + 0) + row * 144 + boff;
        uint32_t bl_ = sb + KREG(2, stream * 2 + 1) + row * 144 + boff;
        #pragma unroll
        for (int kc = 0; kc < 4; kc++) {
            LDSM_X4(qh[kc][0], qh[kc][1], qh[kc][2], qh[kc][3], bh_ + kc * 32);
            LDSM_X4(ql[kc][0], ql[kc][1], ql[kc][2], ql[kc][3], bl_ + kc * 32);
        }
    }

    float out[16][4];
    #pragma unroll
    for (int i = 0; i < 16; i++)
        #pragma unroll
        for (int e = 0; e < 4; e++) out[i][e] = 0.f;
    float m0 = -1e30f, m1 = -1e30f, l0 = 0.f, l1 = 0.f;

    int krow = lane & 7;
    uint32_t kboff = (lane >> 3) * 16;
    int vrow = (lane & 7) + ((lane >> 3) & 1) * 8;
    uint32_t vboff = ((lane >> 4) & 1) * 16;

    for (int kt = 0; kt <= qt; kt++) {
        int buf = kt % 3;
        if (kt < qt) CP_ASYNC_WAIT(1);
        else         CP_ASYNC_WAIT(0);
        __syncthreads();
        if (kt + 2 <= qt) load_tile(kt + 2);

        // ---- scores S = Q K^T, rotating acc targets ----
        float sacc[8][4];
        #pragma unroll
        for (int nt = 0; nt < 8; nt++)
            #pragma unroll
            for (int e = 0; e < 4; e++) sacc[nt][e] = 0.f;

        uint32_t kbh = sb + KREG(buf, stream * 2 + 0);
        uint32_t kbl = sb + KREG(buf, stream * 2 + 1);

        #pragma unroll
        for (int np = 0; np < 4; np++) {
            int ntA = 2 * np, ntB = ntA + 1;
            uint32_t bhA[8], blA[8], bhB[8], blB[8];
            uint32_t raA = (uint32_t)(ntA * 8 + krow) * 144 + kboff;
            uint32_t raB = (uint32_t)(ntB * 8 + krow) * 144 + kboff;
            LDSM_X4(bhA[0], bhA[1], bhA[2], bhA[3], kbh + raA);
            LDSM_X4(bhA[4], bhA[5], bhA[6], bhA[7], kbh + raA + 64);
            LDSM_X4(bhB[0], bhB[1], bhB[2], bhB[3], kbh + raB);
            LDSM_X4(bhB[4], bhB[5], bhB[6], bhB[7], kbh + raB + 64);
            LDSM_X4(blA[0], blA[1], blA[2], blA[3], kbl + raA);
            LDSM_X4(blA[4], blA[5], blA[6], blA[7], kbl + raA + 64);
            LDSM_X4(blB[0], blB[1], blB[2], blB[3], kbl + raB);
            LDSM_X4(blB[4], blB[5], blB[6], blB[7], kbl + raB + 64);
            float tA[4] = {0.f, 0.f, 0.f, 0.f}, tB[4] = {0.f, 0.f, 0.f, 0.f};
            #pragma unroll
            for (int t = 0; t < 3; t++) {
                #pragma unroll
                for (int kc = 0; kc < 4; kc++) {
                    const uint32_t* a = (t == 1) ? ql[kc] : qh[kc];
                    float* dA = (kc & 1) ? tA : sacc[ntA];
                    float* dB = (kc & 1) ? tB : sacc[ntB];
                    uint32_t bA0 = (t == 2) ? blA[2 * kc] : bhA[2 * kc];
                    uint32_t bA1 = (t == 2) ? blA[2 * kc + 1] : bhA[2 * kc + 1];
                    uint32_t bB0 = (t == 2) ? blB[2 * kc] : bhB[2 * kc];
                    uint32_t bB1 = (t == 2) ? blB[2 * kc + 1] : bhB[2 * kc + 1];
                    mma_bf16(dA, a, bA0, bA1);
                    mma_bf16(dB, a, bB0, bB1);
                }
            }
            #pragma unroll
            for (int e = 0; e < 4; e++) { sacc[ntA][e] += tA[e]; sacc[ntB][e] += tB[e]; }
        }

        // ---- online softmax (2 rows per thread) ----
        bool diag = (kt == qt);
        int rlo0 = qw * 16 + (lane >> 2);
        float rm0 = -1e30f, rm1 = -1e30f;
        #pragma unroll
        for (int nt = 0; nt < 8; nt++) {
            #pragma unroll
            for (int e = 0; e < 4; e++) {
                float s = sacc[nt][e] * 0.125f;
                if (diag) {
                    int colL = nt * 8 + 2 * (lane & 3) + (e & 1);
                    int rowL = rlo0 + ((e >> 1) << 3);
                    if (colL > rowL) s = -1e30f;
                }
                sacc[nt][e] = s;
                if (e < 2) rm0 = fmaxf(rm0, s); else rm1 = fmaxf(rm1, s);
            }
        }
        #pragma unroll
        for (int w = 1; w < 4; w <<= 1) {
            rm0 = fmaxf(rm0, __shfl_xor_sync(0xffffffffu, rm0, w));
            rm1 = fmaxf(rm1, __shfl_xor_sync(0xffffffffu, rm1, w));
        }
        float nm0 = fmaxf(m0, rm0), nm1 = fmaxf(m1, rm1);
        float c0 = __expf(m0 - nm0), c1 = __expf(m1 - nm1);
        float ps0 = 0.f, ps1 = 0.f;
        #pragma unroll
        for (int nt = 0; nt < 8; nt++) {
            float p0 = __expf(sacc[nt][0] - nm0);
            float p1 = __expf(sacc[nt][1] - nm0);
            float p2 = __expf(sacc[nt][2] - nm1);
            float p3 = __expf(sacc[nt][3] - nm1);
            sacc[nt][0] = p0; sacc[nt][1] = p1; sacc[nt][2] = p2; sacc[nt][3] = p3;
            ps0 += p0 + p1; ps1 += p2 + p3;
        }
        #pragma unroll
        for (int w = 1; w < 4; w <<= 1) {
            ps0 += __shfl_xor_sync(0xffffffffu, ps0, w);
            ps1 += __shfl_xor_sync(0xffffffffu, ps1, w);
        }
        l0 = l0 * c0 + ps0;
        l1 = l1 * c1 + ps1;
        m0 = nm0; m1 = nm1;
        #pragma unroll
        for (int nt = 0; nt < 16; nt++) {
            out[nt][0] *= c0; out[nt][1] *= c0;
            out[nt][2] *= c1; out[nt][3] *= c1;
        }

        // ---- PV, rotating acc targets ----
        uint32_t vbh = sb + VREG(buf, 0);
        uint32_t vbl = sb + VREG(buf, 1);
        #pragma unroll
        for (int kc2 = 0; kc2 < 4; kc2++) {
            uint32_t pah[4], pal[4];
            split2(sacc[2 * kc2][0], sacc[2 * kc2][1], pah[0], pal[0]);
            split2(sacc[2 * kc2][2], sacc[2 * kc2][3], pah[1], pal[1]);
            split2(sacc[2 * kc2 + 1][0], sacc[2 * kc2 + 1][1], pah[2], pal[2]);
            split2(sacc[2 * kc2 + 1][2], sacc[2 * kc2 + 1][3], pah[3], pal[3]);
            uint32_t vra = (uint32_t)(kc2 * 16 + vrow) * 272 + vboff;
            #pragma unroll
            for (int dpp = 0; dpp < 4; dpp++) {
                int dp0 = 2 * dpp, dp1 = dp0 + 1;
                uint32_t vh0[4], vl0[4], vh1[4], vl1[4];
                LDSM_X4_T(vh0[0], vh0[1], vh0[2], vh0[3], vbh + vra + dp0 * 32);
                LDSM_X4_T(vh1[0], vh1[1], vh1[2], vh1[3], vbh + vra + dp1 * 32);
                LDSM_X4_T(vl0[0], vl0[1], vl0[2], vl0[3], vbl + vra + dp0 * 32);
                LDSM_X4_T(vl1[0], vl1[1], vl1[2], vl1[3], vbl + vra + dp1 * 32);
                #pragma unroll
                for (int t = 0; t < 3; t++) {
                    const uint32_t* p = (t == 1) ? pal : pah;
                    const uint32_t* A0 = (t == 2) ? vl0 : vh0;
                    const uint32_t* A1 = (t == 2) ? vl1 : vh1;
                    mma_bf16(out[2 * dp0],     p, A0[0], A0[1]);
                    mma_bf16(out[2 * dp0 + 1], p, A0[2], A0[3]);
                    mma_bf16(out[2 * dp1],     p, A1[0], A1[1]);
                    mma_bf16(out[2 * dp1 + 1], p, A1[2], A1[3]);
                }
            }
        }
    }

    // ---- epilogue: diff across streams, RMS norm, split-write g_Ahi/g_Alo ----
    float inv0 = 1.f / l0, inv1 = 1.f / l1;
    int r0 = qw * 16 + (lane >> 2);
    float* sX = (float*)smem;
    __syncthreads();
    if (stream == 1) {
        #pragma unroll
        for (int nt = 0; nt < 16; nt++) {
            int col = nt * 8 + 2 * (lane & 3);
            sX[r0 * 132 + col]           = out[nt][0] * inv0;
            sX[r0 * 132 + col + 1]       = out[nt][1] * inv0;
            sX[(r0 + 8) * 132 + col]     = out[nt][2] * inv1;
            sX[(r0 + 8) * 132 + col + 1] = out[nt][3] * inv1;
        }
    }
    __syncthreads();
    if (stream == 0) {
        float lam = g_lambda;
        float ss0 = 0.f, ss1 = 0.f;
        #pragma unroll
        for (int nt = 0; nt < 16; nt++) {
            int col = nt * 8 + 2 * (lane & 3);
            out[nt][0] = out[nt][0] * inv0 - lam * sX[r0 * 132 + col];
            out[nt][1] = out[nt][1] * inv0 - lam * sX[r0 * 132 + col + 1];
            out[nt][2] = out[nt][2] * inv1 - lam * sX[(r0 + 8) * 132 + col];
            out[nt][3] = out[nt][3] * inv1 - lam * sX[(r0 + 8) * 132 + col + 1];
            ss0 += out[nt][0] * out[nt][0] + out[nt][1] * out[nt][1];
            ss1 += out[nt][2] * out[nt][2] + out[nt][3] * out[nt][3];
        }
        #pragma unroll
        for (int w = 1; w < 4; w <<= 1) {
            ss0 += __shfl_xor_sync(0xffffffffu, ss0, w);
            ss1 += __shfl_xor_sync(0xffffffffu, ss1, w);
        }
        float rms0 = rsqrtf(ss0 * (1.f / 128.f) + 1e-5f);
        float rms1 = rsqrtf(ss1 * (1.f / 128.f) + 1e-5f);
        #pragma unroll
        for (int nt = 0; nt < 16; nt++) {
            int col = nt * 8 + 2 * (lane & 3);
            size_t ga = ((size_t)(bS + q0 + r0)) * 2048 + h * 128 + col;
            size_t gb = ((size_t)(bS + q0 + r0 + 8)) * 2048 + h * 128 + col;
            float v0 = out[nt][0] * rms0 * sLn[col] * OUT_SCALE_F;
            float v1 = out[nt][1] * rms0 * sLn[col + 1] * OUT_SCALE_F;
            float v2 = out[nt][2] * rms1 * sLn[col] * OUT_SCALE_F;
            float v3 = out[nt][3] * rms1 * sLn[col + 1] * OUT_SCALE_F;
            uint32_t hi0, lo0, hi1, lo1;
            split2(v0, v1, hi0, lo0);
            split2(v2, v3, hi1, lo1);
            *(uint32_t*)&g_Ahi[ga] = hi0;
            *(uint32_t*)&g_Alo[ga] = lo0;
            *(uint32_t*)&g_Ahi[gb] = hi1;
            *(uint32_t*)&g_Alo[gb] = lo1;
        }
    }
}

// ---------------- launch ----------------
extern "C" void kernel_launch(void* const* d_in, const int* in_sizes, int n_in,
                              void* d_out, int out_size) {
    const float* x   = (const float*)d_in[0];
    const float* Wq  = (const float*)d_in[1];
    const float* Wk  = (const float*)d_in[2];
    const float* Wv  = (const float*)d_in[3];
    const float* Wo  = (const float*)d_in[4];
    const float* lq1 = (const float*)d_in[5];
    const float* lk1 = (const float*)d_in[6];
    const float* lq2 = (const float*)d_in[7];
    const float* lk2 = (const float*)d_in[8];
    const float* lnw = (const float*)d_in[9];
    float* out = (float*)d_out;

    __nv_bfloat16 *xhi, *xlo, *Ahi, *Alo, *Wth, *Wtl;
    cudaGetSymbolAddress((void**)&xhi, g_xhi);
    cudaGetSymbolAddress((void**)&xlo, g_xlo);
    cudaGetSymbolAddress((void**)&Ahi, g_Ahi);
    cudaGetSymbolAddress((void**)&Alo, g_Alo);
    cudaGetSymbolAddress((void**)&Wth, g_Wt_hi);
    cudaGetSymbolAddress((void**)&Wtl, g_Wt_lo);

    cudaFuncSetAttribute(flash_mma_kernel, cudaFuncAttributeMaxDynamicSharedMemorySize,
                         3 * FB_BYTES);
    cudaFuncSetAttribute(mma_gemm_kernel, cudaFuncAttributeMaxDynamicSharedMemorySize,
                         2 * GSTAGE);

    // 5 launches; flash is #4 -> lands on the ncu-captured slot
    prep_all_kernel<<<1025, 64>>>(lq1, lk1, lq2, lk2);                    // 1
    preprocess_kernel<<<49152, 256>>>(x, Wq, Wk, Wv, Wo);                 // 2

    size_t gsmem = 2 * GSTAGE;
    dim3 gqkv(48, ROWS_ / 128);
    mma_gemm_kernel<<<gqkv, 512, gsmem>>>(xhi, xlo, Wth, Wtl, nullptr, 0, 1);  // 3

    dim3 fg(32, 16, 2);
    flash_mma_kernel<<<fg, 256, 3 * FB_BYTES>>>(lnw);                     // 4  <- profiled

    dim3 go(16, ROWS_ / 128);
    mma_gemm_kernel<<<go, 512, gsmem>>>(Ahi, Alo, Wth, Wtl, out, 3, 0);   // 5
}